// round 1
// baseline (speedup 1.0000x reference)
#include <cuda_runtime.h>
#include <math.h>

#define Bb   4
#define Ss   8
#define Ll   350
#define Dd   768
#define Pp   224          // B*S*(S-1)
#define PP2  448          // 2*P

// Scratch (static device globals; no allocation allowed)
__device__ float g_scores[Pp * Ll];
__device__ float g_emb[PP2 * Dd];
__device__ float g_sc[PP2];

// ---------------------------------------------------------------------------
// Kernel 0: pair_embeddings = all_output[:, 0, :]
// ---------------------------------------------------------------------------
__global__ void k_copy(const float* __restrict__ x, float* __restrict__ out) {
    int i = blockIdx.x * 256 + threadIdx.x;
    if (i < Pp * Dd) {
        int p = i / Dd, d = i - p * Dd;
        out[i] = x[(size_t)p * Ll * Dd + d];
    }
}

// ---------------------------------------------------------------------------
// Kernel 1: scores[p,l] = tanh(x[p,l,:]@W1 + b1) @ v1 + vb1
// Only computed for l < second_sep[p] (all other positions are masked to -inf
// downstream and never read). Fused SGEMM: BM=64 rows (l), BN=128 cols,
// BK=16, 256 threads, 4x4x8 thread tiles; epilogue folds tanh * v1 so the
// (78400 x 768) intermediate never exists.
// ---------------------------------------------------------------------------
#define BM 64
#define BN 128
#define BK 16

__global__ __launch_bounds__(256) void k_scores(
    const float* __restrict__ x, const int* __restrict__ ss,
    const float* __restrict__ W1, const float* __restrict__ b1,
    const float* __restrict__ v1, const float* __restrict__ vb1)
{
    int p  = blockIdx.y;
    int l0 = blockIdx.x * BM;
    int send = ss[p];
    if (l0 >= send) return;          // uniform per-CTA early exit (mask saving)

    __shared__ float As[BK][BM];
    __shared__ float Bs[BK][BN];
    __shared__ float sred[BM];

    int tid = threadIdx.x;
    int tx = tid & 15;    // 16 groups over N, 8 cols each
    int ty = tid >> 4;    // 16 groups over M, 4 rows each

    const float* Abase = x + ((size_t)p * Ll + l0) * Dd;

    float partial[4] = {0.f, 0.f, 0.f, 0.f};

    for (int nc = 0; nc < Dd / BN; nc++) {
        int n0 = nc * BN;
        float acc[4][8];
        #pragma unroll
        for (int i = 0; i < 4; i++)
            #pragma unroll
            for (int j = 0; j < 8; j++) acc[i][j] = 0.f;

        for (int kt = 0; kt < Dd / BK; kt++) {
            int k0 = kt * BK;
            // Load A tile: 64 rows x 16 k, one float4 per thread, transposed store
            {
                int m  = tid >> 2;
                int kk = (tid & 3) << 2;
                float4 av = *reinterpret_cast<const float4*>(
                    Abase + (size_t)m * Dd + k0 + kk);
                As[kk + 0][m] = av.x;
                As[kk + 1][m] = av.y;
                As[kk + 2][m] = av.z;
                As[kk + 3][m] = av.w;
            }
            // Load B tile: 16 k x 128 n, two float4 per thread, coalesced
            #pragma unroll
            for (int r = 0; r < 2; r++) {
                int idx = tid + r * 256;      // over 512 float4s
                int kk  = idx >> 5;
                int n4  = (idx & 31) << 2;
                *reinterpret_cast<float4*>(&Bs[kk][n4]) =
                    *reinterpret_cast<const float4*>(
                        W1 + (size_t)(k0 + kk) * Dd + n0 + n4);
            }
            __syncthreads();
            #pragma unroll
            for (int kk = 0; kk < BK; kk++) {
                float4 a  = *reinterpret_cast<const float4*>(&As[kk][ty * 4]);
                float4 b0 = *reinterpret_cast<const float4*>(&Bs[kk][tx * 8]);
                float4 b1v= *reinterpret_cast<const float4*>(&Bs[kk][tx * 8 + 4]);
                float am[4] = {a.x, a.y, a.z, a.w};
                float bn[8] = {b0.x, b0.y, b0.z, b0.w, b1v.x, b1v.y, b1v.z, b1v.w};
                #pragma unroll
                for (int i = 0; i < 4; i++)
                    #pragma unroll
                    for (int j = 0; j < 8; j++)
                        acc[i][j] += am[i] * bn[j];
            }
            __syncthreads();
        }
        // Fused epilogue: tanh + dot with v1 for this column chunk
        #pragma unroll
        for (int j = 0; j < 8; j++) {
            int n = n0 + tx * 8 + j;
            float bb = b1[n];
            float vv = v1[n];
            #pragma unroll
            for (int i = 0; i < 4; i++)
                partial[i] += tanhf(acc[i][j] + bb) * vv;
        }
    }

    // Reduce partials across the 16 tx groups
    if (tid < BM) sred[tid] = 0.f;
    __syncthreads();
    #pragma unroll
    for (int i = 0; i < 4; i++)
        atomicAdd(&sred[ty * 4 + i], partial[i]);
    __syncthreads();
    if (tid < BM) {
        int l = l0 + tid;
        if (l < Ll) g_scores[p * Ll + l] = sred[tid] + vb1[0];
    }
}

// ---------------------------------------------------------------------------
// Kernel 2: masked softmax pooling over L for both segments of each pair
// grid (2, P), 256 threads. emb[2p+seg, :] = softmax(scores[range]) @ x[p]
// ---------------------------------------------------------------------------
__global__ __launch_bounds__(256) void k_pool(const float* __restrict__ x,
                                              const int* __restrict__ fs,
                                              const int* __restrict__ ssp)
{
    int p   = blockIdx.y;
    int sgi = blockIdx.x;            // 0: [1, fs), 1: (fs, ss)
    int f = fs[p], s2 = ssp[p];
    int lo = sgi ? f + 1 : 1;
    int hi = sgi ? s2 : f;
    int cnt = hi - lo;               // in [4, 148]

    __shared__ float w[160];
    __shared__ float red[256];
    int tid = threadIdx.x;

    const float* sc = g_scores + p * Ll + lo;

    float lm = -1e30f;
    for (int i = tid; i < cnt; i += 256) lm = fmaxf(lm, sc[i]);
    red[tid] = lm; __syncthreads();
    for (int o = 128; o > 0; o >>= 1) {
        if (tid < o) red[tid] = fmaxf(red[tid], red[tid + o]);
        __syncthreads();
    }
    float smax = red[0];
    __syncthreads();

    float le = 0.f;
    for (int i = tid; i < cnt; i += 256) {
        float e = __expf(sc[i] - smax);
        w[i] = e;
        le += e;
    }
    red[tid] = le; __syncthreads();
    for (int o = 128; o > 0; o >>= 1) {
        if (tid < o) red[tid] += red[tid + o];
        __syncthreads();
    }
    float inv = 1.0f / red[0];
    __syncthreads();

    // Weighted accumulation; thread owns d = tid, tid+256, tid+512
    float e0 = 0.f, e1 = 0.f, e2 = 0.f;
    const float* xr = x + ((size_t)p * Ll + lo) * Dd;
    for (int i = 0; i < cnt; i++) {
        float wl = w[i] * inv;
        const float* row = xr + (size_t)i * Dd;
        e0 += wl * row[tid];
        e1 += wl * row[tid + 256];
        e2 += wl * row[tid + 512];
    }
    float* er = g_emb + (size_t)(2 * p + sgi) * Dd;
    er[tid]       = e0;
    er[tid + 256] = e1;
    er[tid + 512] = e2;
}

// ---------------------------------------------------------------------------
// Kernel 3: sc[r] = tanh(emb[r]@W2 + b2) @ v2 + vb2, 8 rows per CTA so W2 is
// streamed from L2 only 56x instead of 448x.
// ---------------------------------------------------------------------------
#define R3 8
__global__ __launch_bounds__(256) void k_score2(
    const float* __restrict__ W2, const float* __restrict__ b2,
    const float* __restrict__ v2, const float* __restrict__ vb2)
{
    int r0 = blockIdx.x * R3;
    __shared__ float er[R3][Dd];
    __shared__ float tot[R3];
    int tid = threadIdx.x;

    for (int i = tid; i < R3 * Dd; i += 256)
        (&er[0][0])[i] = g_emb[(size_t)r0 * Dd + i];
    if (tid < R3) tot[tid] = 0.f;
    __syncthreads();

    float acc[R3];
    #pragma unroll
    for (int q = 0; q < R3; q++) acc[q] = 0.f;

    for (int n = tid; n < Dd; n += 256) {
        float dot[R3];
        float bb = b2[n];
        #pragma unroll
        for (int q = 0; q < R3; q++) dot[q] = bb;
        for (int k = 0; k < Dd; k++) {
            float wv = W2[(size_t)k * Dd + n];   // coalesced across threads
            #pragma unroll
            for (int q = 0; q < R3; q++) dot[q] += er[q][k] * wv;  // smem bcast
        }
        float vv = v2[n];
        #pragma unroll
        for (int q = 0; q < R3; q++) acc[q] += tanhf(dot[q]) * vv;
    }
    #pragma unroll
    for (int q = 0; q < R3; q++) atomicAdd(&tot[q], acc[q]);
    __syncthreads();
    if (tid < R3) g_sc[r0 + tid] = tot[tid] + vb2[0];
}

// ---------------------------------------------------------------------------
// Kernel 4: segment softmax + weighted sum -> out2[B,S,D]
// seg(2p)=z*8+j, seg(2p+1)=z*8+k for p=(z,j,k) enumerated j!=k.
// Each segment has exactly 14 members. 32 CTAs.
// ---------------------------------------------------------------------------
__global__ void k_out2(float* __restrict__ out) {
    int seg = blockIdx.x;
    int tid = threadIdx.x;
    __shared__ int   mem[14];
    __shared__ float wv[14];

    if (tid == 0) {
        int c = 0;
        for (int idx = 0; idx < PP2; idx++) {
            int pp = idx >> 1, cc = idx & 1;
            int z = pp / 56, r = pp % 56, j = r / 7, m = r % 7;
            int k = m + (m >= j ? 1 : 0);
            int sg = z * 8 + (cc == 0 ? j : k);
            if (sg == seg && c < 14) mem[c++] = idx;
        }
        float mx = -1e30f;
        for (int i = 0; i < 14; i++) mx = fmaxf(mx, g_sc[mem[i]]);
        float den = 0.f;
        for (int i = 0; i < 14; i++) {
            float e = __expf(g_sc[mem[i]] - mx);
            wv[i] = e;
            den += e;
        }
        float inv = 1.f / den;
        for (int i = 0; i < 14; i++) wv[i] *= inv;
    }
    __syncthreads();

    for (int d = tid; d < Dd; d += 256) {
        float a = 0.f;
        #pragma unroll
        for (int i = 0; i < 14; i++)
            a += wv[i] * g_emb[(size_t)mem[i] * Dd + d];
        out[Pp * Dd + seg * Dd + d] = a;
    }
}

// ---------------------------------------------------------------------------
// Launch
// ---------------------------------------------------------------------------
extern "C" void kernel_launch(void* const* d_in, const int* in_sizes, int n_in,
                              void* d_out, int out_size) {
    const float* x   = (const float*)d_in[0];   // all_output (P,L,D)
    const int*   fs  = (const int*)  d_in[1];   // first_sep (P,)
    const int*   ss  = (const int*)  d_in[2];   // second_sep (P,)
    const float* W1  = (const float*)d_in[3];
    const float* b1  = (const float*)d_in[4];
    const float* v1  = (const float*)d_in[5];
    const float* vb1 = (const float*)d_in[6];
    const float* W2  = (const float*)d_in[7];
    const float* b2  = (const float*)d_in[8];
    const float* v2  = (const float*)d_in[9];
    const float* vb2 = (const float*)d_in[10];
    float* out = (float*)d_out;                 // [P*D pair_emb | B*S*D out2]

    k_copy<<<(Pp * Dd + 255) / 256, 256>>>(x, out);

    dim3 g1((Ll + BM - 1) / BM, Pp);            // 6 x 224, ~50% exit early
    k_scores<<<g1, 256>>>(x, ss, W1, b1, v1, vb1);

    dim3 g2(2, Pp);
    k_pool<<<g2, 256>>>(x, fs, ss);

    k_score2<<<PP2 / R3, 256>>>(W2, b2, v2, vb2);

    k_out2<<<Bb * Ss, 256>>>(out);
}

// round 3
// speedup vs baseline: 2.3174x; 2.3174x over previous
#include <cuda_runtime.h>
#include <cuda_bf16.h>
#include <cstdint>
#include <math.h>

#define Bb   4
#define Ss   8
#define Ll   350
#define Dd   768
#define Pp   224
#define PP2  448

// ---------------------------------------------------------------------------
// Scratch (static device globals; no allocation allowed)
// ---------------------------------------------------------------------------
__device__ float g_scores[Pp * Ll];
__device__ float g_emb[PP2 * Dd];
__device__ float g_sc[PP2];
// Pre-transposed bf16-split weights, layout [n][k] (k contiguous)
__device__ __nv_bfloat16 g_W1h[Dd * Dd];
__device__ __nv_bfloat16 g_W1l[Dd * Dd];
__device__ __nv_bfloat16 g_W2h[Dd * Dd];
__device__ __nv_bfloat16 g_W2l[Dd * Dd];

__device__ __forceinline__ uint32_t pack2(__nv_bfloat16 a, __nv_bfloat16 b) {
    return (uint32_t)__bfloat16_as_ushort(a) | ((uint32_t)__bfloat16_as_ushort(b) << 16);
}

__device__ __forceinline__ float tanh_f(float x) {
    x = fminf(15.f, fmaxf(-15.f, x));
    float e = __expf(2.f * x);
    return (e - 1.f) / (e + 1.f);
}

// mma.m16n8k16 bf16 -> fp32 accumulate (HMMA; valid on plain sm_103 target)
__device__ __forceinline__ void mma_bf16(float* c, const uint32_t* a,
                                         uint32_t b0, uint32_t b1) {
    asm volatile(
        "mma.sync.aligned.m16n8k16.row.col.f32.bf16.bf16.f32 "
        "{%0,%1,%2,%3}, {%4,%5,%6,%7}, {%8,%9}, {%0,%1,%2,%3};"
        : "+f"(c[0]), "+f"(c[1]), "+f"(c[2]), "+f"(c[3])
        : "r"(a[0]), "r"(a[1]), "r"(a[2]), "r"(a[3]), "r"(b0), "r"(b1));
}

// ---------------------------------------------------------------------------
// Kernel 0: pair_embeddings = all_output[:, 0, :]
// ---------------------------------------------------------------------------
__global__ void k_copy(const float* __restrict__ x, float* __restrict__ out) {
    int i = blockIdx.x * 256 + threadIdx.x;
    if (i < Pp * Dd) {
        int p = i / Dd, d = i - p * Dd;
        out[i] = x[(size_t)p * Ll * Dd + d];
    }
}

// ---------------------------------------------------------------------------
// Weight prep: W[k][n] -> WT[n][k], split fp32 -> bf16 hi + lo.
// 64x64 smem-transpose tiles; coalesced reads and writes.
// ---------------------------------------------------------------------------
__global__ __launch_bounds__(256) void k_convW(const float* __restrict__ W1,
                                               const float* __restrict__ W2) {
    __shared__ float s[64][65];
    int k0 = blockIdx.x * 64, n0 = blockIdx.y * 64;
    const float* W = blockIdx.z ? W2 : W1;
    __nv_bfloat16* OH = blockIdx.z ? g_W2h : g_W1h;
    __nv_bfloat16* OL = blockIdx.z ? g_W2l : g_W1l;
    int tid = threadIdx.x;
    int nl = tid & 63, kl = tid >> 6;
    #pragma unroll
    for (int j = 0; j < 16; j++)
        s[kl + j * 4][nl] = W[(size_t)(k0 + kl + j * 4) * Dd + n0 + nl];
    __syncthreads();
    int q = tid & 31, nr = tid >> 5;
    #pragma unroll
    for (int j = 0; j < 8; j++) {
        int n = nr + j * 8;
        float x0 = s[2 * q][n], x1 = s[2 * q + 1][n];
        __nv_bfloat16 h0 = __float2bfloat16(x0);
        __nv_bfloat16 h1 = __float2bfloat16(x1);
        __nv_bfloat16 l0 = __float2bfloat16(x0 - __bfloat162float(h0));
        __nv_bfloat16 l1 = __float2bfloat16(x1 - __bfloat162float(h1));
        size_t off = (size_t)(n0 + n) * Dd + k0 + 2 * q;
        *reinterpret_cast<uint32_t*>(reinterpret_cast<char*>(OH) + off * 2) = pack2(h0, h1);
        *reinterpret_cast<uint32_t*>(reinterpret_cast<char*>(OL) + off * 2) = pack2(l0, l1);
    }
}

// ---------------------------------------------------------------------------
// Fused HMMA GEMM: out[row] = tanh(A[row,:] @ W + b) @ v + vb
// CTA: 128 rows x 128 N-chunk (6 chunks), BK=32 double-buffered smem,
// 8 warps each 32x64 warp-tile of m16n8k16 mma, bf16 hi/lo split (3 MMAs).
// ---------------------------------------------------------------------------
#define BK      32
#define STRIDE  80         // padded smem row stride (bytes) -> conflict-free
#define A_TILE  10240      // 128 * 80
#define STAGE   40960      // Ah | Al | Bh | Bl
#define SMEM_TOT (2 * STAGE + 1024)

template <bool SCORES>
__global__ __launch_bounds__(256, 1) void k_gemm(
    const float* __restrict__ x, const int* __restrict__ ss,
    const float* __restrict__ bvec, const float* __restrict__ vvec,
    const float* __restrict__ vbp)
{
    extern __shared__ char smem[];
    int tid = threadIdx.x;
    int l0 = blockIdx.x * 128;

    const float* Abase;
    int maxRow, outMax;
    float* outp;
    const __nv_bfloat16 *WH, *WL;
    if (SCORES) {
        int p = blockIdx.y;
        if (l0 >= ss[p]) return;           // uniform CTA-level mask skip
        Abase = x + (size_t)p * Ll * Dd;
        maxRow = Ll - 1; outp = g_scores + p * Ll; outMax = Ll;
        WH = g_W1h; WL = g_W1l;
    } else {
        Abase = g_emb;
        maxRow = PP2 - 1; outp = g_sc; outMax = PP2;
        WH = g_W2h; WL = g_W2l;
    }

    int warp = tid >> 5, lane = tid & 31;
    int g = lane >> 2, t = lane & 3;
    int m0 = (warp >> 1) * 32;
    int wn = warp & 1;
    int n0w = wn * 64;

    float4 aV[4];
    uint4  bV[4];
    float  acc[2][8][4];
    float  partial[4] = {0.f, 0.f, 0.f, 0.f};

    for (int nc = 0; nc < 6; nc++) {
        #pragma unroll
        for (int sm = 0; sm < 2; sm++)
            #pragma unroll
            for (int ns = 0; ns < 8; ns++)
                #pragma unroll
                for (int j = 0; j < 4; j++) acc[sm][ns][j] = 0.f;

        // ---- stage LDG ----
        auto LDG = [&](int kc) {
            int kb = kc * BK;
            #pragma unroll
            for (int i = 0; i < 4; i++) {
                int u = tid + i * 256;
                int r = u >> 3, kq = u & 7;
                int row = l0 + r; if (row > maxRow) row = maxRow;
                aV[i] = *reinterpret_cast<const float4*>(
                    Abase + (size_t)row * Dd + kb + kq * 4);
            }
            #pragma unroll
            for (int i = 0; i < 2; i++) {
                int u = tid + i * 256;
                int r = u >> 2, q = u & 3;
                size_t off = ((size_t)(nc * 128 + r) * Dd + kb + q * 8) * 2;
                bV[i]     = *reinterpret_cast<const uint4*>(
                    reinterpret_cast<const char*>(WH) + off);
                bV[i + 2] = *reinterpret_cast<const uint4*>(
                    reinterpret_cast<const char*>(WL) + off);
            }
        };
        // ---- stage STS (fp32 A -> bf16 hi/lo) ----
        auto STS = [&](int st) {
            char* sA = smem + st * STAGE;
            #pragma unroll
            for (int i = 0; i < 4; i++) {
                int u = tid + i * 256;
                int r = u >> 3, kq = u & 7;
                float4 v = aV[i];
                __nv_bfloat16 hx = __float2bfloat16(v.x), hy = __float2bfloat16(v.y);
                __nv_bfloat16 hz = __float2bfloat16(v.z), hw = __float2bfloat16(v.w);
                __nv_bfloat16 lx = __float2bfloat16(v.x - __bfloat162float(hx));
                __nv_bfloat16 ly = __float2bfloat16(v.y - __bfloat162float(hy));
                __nv_bfloat16 lz = __float2bfloat16(v.z - __bfloat162float(hz));
                __nv_bfloat16 lw = __float2bfloat16(v.w - __bfloat162float(hw));
                int off = r * STRIDE + kq * 8;
                *reinterpret_cast<uint2*>(sA + off) =
                    make_uint2(pack2(hx, hy), pack2(hz, hw));
                *reinterpret_cast<uint2*>(sA + A_TILE + off) =
                    make_uint2(pack2(lx, ly), pack2(lz, lw));
            }
            char* sB = sA + 2 * A_TILE;
            #pragma unroll
            for (int i = 0; i < 2; i++) {
                int u = tid + i * 256;
                int r = u >> 2, q = u & 3;
                int off = r * STRIDE + q * 16;
                *reinterpret_cast<uint4*>(sB + off)          = bV[i];
                *reinterpret_cast<uint4*>(sB + A_TILE + off) = bV[i + 2];
            }
        };
        // ---- compute one BK stage ----
        auto COMPUTE = [&](int st) {
            const char* sA  = smem + st * STAGE;
            const char* sAl = sA + A_TILE;
            const char* sB  = sA + 2 * A_TILE;
            const char* sBl = sB + A_TILE;
            #pragma unroll
            for (int kk = 0; kk < BK; kk += 16) {
                uint32_t ah[2][4], al[2][4];
                #pragma unroll
                for (int sm = 0; sm < 2; sm++) {
                    int o = (m0 + sm * 16 + g) * STRIDE + (kk + 2 * t) * 2;
                    ah[sm][0] = *reinterpret_cast<const uint32_t*>(sA + o);
                    ah[sm][1] = *reinterpret_cast<const uint32_t*>(sA + o + 8 * STRIDE);
                    ah[sm][2] = *reinterpret_cast<const uint32_t*>(sA + o + 16);
                    ah[sm][3] = *reinterpret_cast<const uint32_t*>(sA + o + 8 * STRIDE + 16);
                    al[sm][0] = *reinterpret_cast<const uint32_t*>(sAl + o);
                    al[sm][1] = *reinterpret_cast<const uint32_t*>(sAl + o + 8 * STRIDE);
                    al[sm][2] = *reinterpret_cast<const uint32_t*>(sAl + o + 16);
                    al[sm][3] = *reinterpret_cast<const uint32_t*>(sAl + o + 8 * STRIDE + 16);
                }
                #pragma unroll
                for (int ns = 0; ns < 8; ns++) {
                    int o = (n0w + ns * 8 + g) * STRIDE + (kk + 2 * t) * 2;
                    uint32_t bh0 = *reinterpret_cast<const uint32_t*>(sB + o);
                    uint32_t bh1 = *reinterpret_cast<const uint32_t*>(sB + o + 16);
                    uint32_t bl0 = *reinterpret_cast<const uint32_t*>(sBl + o);
                    uint32_t bl1 = *reinterpret_cast<const uint32_t*>(sBl + o + 16);
                    #pragma unroll
                    for (int sm = 0; sm < 2; sm++) {
                        mma_bf16(acc[sm][ns], ah[sm], bh0, bh1);   // hi*hi
                        mma_bf16(acc[sm][ns], al[sm], bh0, bh1);   // lo*hi
                        mma_bf16(acc[sm][ns], ah[sm], bl0, bl1);   // hi*lo
                    }
                }
            }
        };

        LDG(0);
        STS(0);
        __syncthreads();
        for (int kc = 0; kc < 24; kc++) {
            if (kc + 1 < 24) LDG(kc + 1);
            COMPUTE(kc & 1);
            __syncthreads();
            if (kc + 1 < 24) {
                STS((kc + 1) & 1);
                __syncthreads();
            }
        }

        // fused epilogue: tanh(acc + b) * v, accumulate per-row partials
        #pragma unroll
        for (int sm = 0; sm < 2; sm++)
            #pragma unroll
            for (int ns = 0; ns < 8; ns++) {
                int col = nc * 128 + n0w + ns * 8 + 2 * t;
                float bb0 = __ldg(&bvec[col]),     bb1 = __ldg(&bvec[col + 1]);
                float vv0 = __ldg(&vvec[col]),     vv1 = __ldg(&vvec[col + 1]);
                partial[sm * 2 + 0] += tanh_f(acc[sm][ns][0] + bb0) * vv0
                                     + tanh_f(acc[sm][ns][1] + bb1) * vv1;
                partial[sm * 2 + 1] += tanh_f(acc[sm][ns][2] + bb0) * vv0
                                     + tanh_f(acc[sm][ns][3] + bb1) * vv1;
            }
        __syncthreads();     // stage buffers idle before next nc's STS(0)
    }

    // reduce over t-quad (butterfly), then across the two warp_n halves
    #pragma unroll
    for (int j = 0; j < 4; j++) {
        partial[j] += __shfl_xor_sync(0xffffffffu, partial[j], 1);
        partial[j] += __shfl_xor_sync(0xffffffffu, partial[j], 2);
    }
    float* red = reinterpret_cast<float*>(smem + 2 * STAGE);
    if (t == 0) {
        red[wn * 128 + m0 + g]      = partial[0];
        red[wn * 128 + m0 + 8 + g]  = partial[1];
        red[wn * 128 + m0 + 16 + g] = partial[2];
        red[wn * 128 + m0 + 24 + g] = partial[3];
    }
    __syncthreads();
    if (tid < 128) {
        int gr = l0 + tid;
        if (gr < outMax) outp[gr] = red[tid] + red[128 + tid] + vbp[0];
    }
}

// ---------------------------------------------------------------------------
// Masked softmax pooling (unchanged, passing since R1)
// ---------------------------------------------------------------------------
__global__ __launch_bounds__(256) void k_pool(const float* __restrict__ x,
                                              const int* __restrict__ fs,
                                              const int* __restrict__ ssp)
{
    int p   = blockIdx.y;
    int sgi = blockIdx.x;
    int f = fs[p], s2 = ssp[p];
    int lo = sgi ? f + 1 : 1;
    int hi = sgi ? s2 : f;
    int cnt = hi - lo;

    __shared__ float w[160];
    __shared__ float red[256];
    int tid = threadIdx.x;

    const float* sc = g_scores + p * Ll + lo;

    float lm = -1e30f;
    for (int i = tid; i < cnt; i += 256) lm = fmaxf(lm, sc[i]);
    red[tid] = lm; __syncthreads();
    for (int o = 128; o > 0; o >>= 1) {
        if (tid < o) red[tid] = fmaxf(red[tid], red[tid + o]);
        __syncthreads();
    }
    float smax = red[0];
    __syncthreads();

    float le = 0.f;
    for (int i = tid; i < cnt; i += 256) {
        float e = __expf(sc[i] - smax);
        w[i] = e;
        le += e;
    }
    red[tid] = le; __syncthreads();
    for (int o = 128; o > 0; o >>= 1) {
        if (tid < o) red[tid] += red[tid + o];
        __syncthreads();
    }
    float inv = 1.0f / red[0];
    __syncthreads();

    float e0 = 0.f, e1 = 0.f, e2 = 0.f;
    const float* xr = x + ((size_t)p * Ll + lo) * Dd;
    for (int i = 0; i < cnt; i++) {
        float wl = w[i] * inv;
        const float* row = xr + (size_t)i * Dd;
        e0 += wl * row[tid];
        e1 += wl * row[tid + 256];
        e2 += wl * row[tid + 512];
    }
    float* er = g_emb + (size_t)(2 * p + sgi) * Dd;
    er[tid]       = e0;
    er[tid + 256] = e1;
    er[tid + 512] = e2;
}

// ---------------------------------------------------------------------------
// Segment softmax + weighted sum (unchanged)
// ---------------------------------------------------------------------------
__global__ void k_out2(float* __restrict__ out) {
    int seg = blockIdx.x;
    int tid = threadIdx.x;
    __shared__ int   mem[14];
    __shared__ float wv[14];

    if (tid == 0) {
        int c = 0;
        for (int idx = 0; idx < PP2; idx++) {
            int pp = idx >> 1, cc = idx & 1;
            int z = pp / 56, r = pp % 56, j = r / 7, m = r % 7;
            int k = m + (m >= j ? 1 : 0);
            int sg = z * 8 + (cc == 0 ? j : k);
            if (sg == seg && c < 14) mem[c++] = idx;
        }
        float mx = -1e30f;
        for (int i = 0; i < 14; i++) mx = fmaxf(mx, g_sc[mem[i]]);
        float den = 0.f;
        for (int i = 0; i < 14; i++) {
            float e = __expf(g_sc[mem[i]] - mx);
            wv[i] = e;
            den += e;
        }
        float inv = 1.f / den;
        for (int i = 0; i < 14; i++) wv[i] *= inv;
    }
    __syncthreads();

    for (int d = tid; d < Dd; d += 256) {
        float a = 0.f;
        #pragma unroll
        for (int i = 0; i < 14; i++)
            a += wv[i] * g_emb[(size_t)mem[i] * Dd + d];
        out[Pp * Dd + seg * Dd + d] = a;
    }
}

// ---------------------------------------------------------------------------
// Launch
// ---------------------------------------------------------------------------
extern "C" void kernel_launch(void* const* d_in, const int* in_sizes, int n_in,
                              void* d_out, int out_size) {
    const float* x   = (const float*)d_in[0];
    const int*   fs  = (const int*)  d_in[1];
    const int*   ss  = (const int*)  d_in[2];
    const float* W1  = (const float*)d_in[3];
    const float* b1  = (const float*)d_in[4];
    const float* v1  = (const float*)d_in[5];
    const float* vb1 = (const float*)d_in[6];
    const float* W2  = (const float*)d_in[7];
    const float* b2  = (const float*)d_in[8];
    const float* v2  = (const float*)d_in[9];
    const float* vb2 = (const float*)d_in[10];
    float* out = (float*)d_out;

    static bool attr_done = false;
    if (!attr_done) {
        cudaFuncSetAttribute(k_gemm<true>,
            cudaFuncAttributeMaxDynamicSharedMemorySize, SMEM_TOT);
        cudaFuncSetAttribute(k_gemm<false>,
            cudaFuncAttributeMaxDynamicSharedMemorySize, SMEM_TOT);
        attr_done = true;
    }

    k_copy<<<(Pp * Dd + 255) / 256, 256>>>(x, out);

    k_convW<<<dim3(12, 12, 2), 256>>>(W1, W2);

    dim3 g1(3, Pp);
    k_gemm<true><<<g1, 256, SMEM_TOT>>>(x, ss, b1, v1, vb1);

    dim3 g2(2, Pp);
    k_pool<<<g2, 256>>>(x, fs, ss);

    k_gemm<false><<<dim3(4, 1), 256, SMEM_TOT>>>(x, ss, b2, v2, vb2);

    k_out2<<<Bb * Ss, 256>>>(out);
}

// round 4
// speedup vs baseline: 3.4228x; 1.4770x over previous
#include <cuda_runtime.h>
#include <cuda_bf16.h>
#include <cstdint>
#include <math.h>

#define Bb   4
#define Ss   8
#define Ll   350
#define Dd   768
#define Pp   224
#define PP2  448
#define RMAX (Pp * 300)        // second_sep < 300 strictly

// ---------------------------------------------------------------------------
// Scratch (static device globals; no allocation allowed)
// ---------------------------------------------------------------------------
__device__ float g_scores[Pp * Ll];
__device__ float g_emb[PP2 * Dd];
__device__ float g_sc[PP2];
__device__ int   g_poff[Pp + 1];
__device__ int   g_rowmap[RMAX];
// Pre-split operands (bf16 hi/lo), all [row][k] with k contiguous
__device__ __nv_bfloat16 g_Ah[RMAX * Dd];
__device__ __nv_bfloat16 g_Al[RMAX * Dd];
__device__ __nv_bfloat16 g_Eh[PP2 * Dd];
__device__ __nv_bfloat16 g_El[PP2 * Dd];
__device__ __nv_bfloat16 g_W1h[Dd * Dd];
__device__ __nv_bfloat16 g_W1l[Dd * Dd];
__device__ __nv_bfloat16 g_W2h[Dd * Dd];
__device__ __nv_bfloat16 g_W2l[Dd * Dd];

__device__ __forceinline__ uint32_t smem_u32(const void* p) {
    uint32_t a;
    asm("{ .reg .u64 t; cvta.to.shared.u64 t, %1; cvt.u32.u64 %0, t; }"
        : "=r"(a) : "l"(p));
    return a;
}

__device__ __forceinline__ uint32_t pack2(__nv_bfloat16 a, __nv_bfloat16 b) {
    return (uint32_t)__bfloat16_as_ushort(a) | ((uint32_t)__bfloat16_as_ushort(b) << 16);
}

__device__ __forceinline__ float tanh_f(float x) {
    x = fminf(15.f, fmaxf(-15.f, x));
    float e = __expf(2.f * x);
    return (e - 1.f) / (e + 1.f);
}

__device__ __forceinline__ void mma_bf16(float* c, const uint32_t* a,
                                         uint32_t b0, uint32_t b1) {
    asm volatile(
        "mma.sync.aligned.m16n8k16.row.col.f32.bf16.bf16.f32 "
        "{%0,%1,%2,%3}, {%4,%5,%6,%7}, {%8,%9}, {%0,%1,%2,%3};"
        : "+f"(c[0]), "+f"(c[1]), "+f"(c[2]), "+f"(c[3])
        : "r"(a[0]), "r"(a[1]), "r"(a[2]), "r"(a[3]), "r"(b0), "r"(b1));
}

#define CP16(dst, src) \
    asm volatile("cp.async.cg.shared.global [%0], [%1], 16;" \
                 :: "r"(dst), "l"(src) : "memory")
#define CP_COMMIT() asm volatile("cp.async.commit_group;" ::: "memory")
#define CP_WAIT2()  asm volatile("cp.async.wait_group 2;"  ::: "memory")

// ---------------------------------------------------------------------------
// Kernel 0: pair_embeddings = all_output[:, 0, :]
// ---------------------------------------------------------------------------
__global__ void k_copy(const float* __restrict__ x, float* __restrict__ out) {
    int i = blockIdx.x * 256 + threadIdx.x;
    if (i < Pp * Dd) {
        int p = i / Dd, d = i - p * Dd;
        out[i] = x[(size_t)p * Ll * Dd + d];
    }
}

// ---------------------------------------------------------------------------
// Prefix offsets of second_sep (compacted row layout)
// ---------------------------------------------------------------------------
__global__ void k_offsets(const int* __restrict__ ss) {
    __shared__ int s[Pp];
    int t = threadIdx.x;
    if (t < Pp) s[t] = ss[t];
    __syncthreads();
    if (t == 0) {
        int a = 0;
        for (int p = 0; p < Pp; p++) { int v = s[p]; s[p] = a; a += v; }
        g_poff[Pp] = a;
    }
    __syncthreads();
    if (t < Pp) g_poff[t] = s[t];
}

// ---------------------------------------------------------------------------
// Compact + split A: rows (p, l<ss[p]) -> g_Ah/g_Al, and row map
// ---------------------------------------------------------------------------
__global__ __launch_bounds__(192) void k_convA(const float* __restrict__ x,
                                               const int* __restrict__ ss) {
    int l = blockIdx.x, p = blockIdx.y;
    if (l >= ss[p]) return;
    int r = g_poff[p] + l;
    int tid = threadIdx.x;
    if (tid == 0) g_rowmap[r] = p * Ll + l;
    float4 v = *reinterpret_cast<const float4*>(
        x + ((size_t)p * Ll + l) * Dd + tid * 4);
    __nv_bfloat16 hx = __float2bfloat16(v.x), hy = __float2bfloat16(v.y);
    __nv_bfloat16 hz = __float2bfloat16(v.z), hw = __float2bfloat16(v.w);
    __nv_bfloat16 lx = __float2bfloat16(v.x - __bfloat162float(hx));
    __nv_bfloat16 ly = __float2bfloat16(v.y - __bfloat162float(hy));
    __nv_bfloat16 lz = __float2bfloat16(v.z - __bfloat162float(hz));
    __nv_bfloat16 lw = __float2bfloat16(v.w - __bfloat162float(hw));
    size_t off = ((size_t)r * Dd + tid * 4) * 2;
    *reinterpret_cast<uint2*>(reinterpret_cast<char*>(g_Ah) + off) =
        make_uint2(pack2(hx, hy), pack2(hz, hw));
    *reinterpret_cast<uint2*>(reinterpret_cast<char*>(g_Al) + off) =
        make_uint2(pack2(lx, ly), pack2(lz, lw));
}

// ---------------------------------------------------------------------------
// Weight prep: W[k][n] -> WT[n][k], split fp32 -> bf16 hi + lo
// ---------------------------------------------------------------------------
__global__ __launch_bounds__(256) void k_convW(const float* __restrict__ W1,
                                               const float* __restrict__ W2) {
    __shared__ float s[64][65];
    int k0 = blockIdx.x * 64, n0 = blockIdx.y * 64;
    const float* W = blockIdx.z ? W2 : W1;
    __nv_bfloat16* OH = blockIdx.z ? g_W2h : g_W1h;
    __nv_bfloat16* OL = blockIdx.z ? g_W2l : g_W1l;
    int tid = threadIdx.x;
    int nl = tid & 63, kl = tid >> 6;
    #pragma unroll
    for (int j = 0; j < 16; j++)
        s[kl + j * 4][nl] = W[(size_t)(k0 + kl + j * 4) * Dd + n0 + nl];
    __syncthreads();
    int q = tid & 31, nr = tid >> 5;
    #pragma unroll
    for (int j = 0; j < 8; j++) {
        int n = nr + j * 8;
        float x0 = s[2 * q][n], x1 = s[2 * q + 1][n];
        __nv_bfloat16 h0 = __float2bfloat16(x0);
        __nv_bfloat16 h1 = __float2bfloat16(x1);
        __nv_bfloat16 l0 = __float2bfloat16(x0 - __bfloat162float(h0));
        __nv_bfloat16 l1 = __float2bfloat16(x1 - __bfloat162float(h1));
        size_t off = (size_t)(n0 + n) * Dd + k0 + 2 * q;
        *reinterpret_cast<uint32_t*>(reinterpret_cast<char*>(OH) + off * 2) = pack2(h0, h1);
        *reinterpret_cast<uint32_t*>(reinterpret_cast<char*>(OL) + off * 2) = pack2(l0, l1);
    }
}

// ---------------------------------------------------------------------------
// Fused HMMA GEMM, cp.async 4-stage pipeline.
// CTA: 128 compact rows x 128 N (6 chunks), BK=32.
// smem stage (40960B): Ah | Al | Bh | Bl, each 128 rows x 80B padded.
// ---------------------------------------------------------------------------
#define BK      32
#define STRIDE  80
#define TILEB   10240
#define STAGEB  40960
#define NST     4
#define SMEM_TOT (NST * STAGEB + 1024)

template <bool COMPACT>
__global__ __launch_bounds__(256, 1) void k_gemm(
    const float* __restrict__ bvec, const float* __restrict__ vvec,
    const float* __restrict__ vbp)
{
    extern __shared__ char smem[];
    int tid = threadIdx.x;
    int l0 = blockIdx.x * 128;

    int R = COMPACT ? g_poff[Pp] : PP2;
    if (l0 >= R) return;

    const __nv_bfloat16* AH = COMPACT ? g_Ah : g_Eh;
    const __nv_bfloat16* AL = COMPACT ? g_Al : g_El;
    const __nv_bfloat16* WH = COMPACT ? g_W1h : g_W2h;
    const __nv_bfloat16* WL = COMPACT ? g_W1l : g_W2l;
    float* outp = COMPACT ? g_scores : g_sc;

    uint32_t sb = smem_u32(smem);

    // fixed per-thread copy lanes: rows r0,r1; 16B chunk q
    int q = tid & 3, r0 = tid >> 2, r1 = r0 + 64;
    int gr0 = l0 + r0; if (gr0 >= R) gr0 = R - 1;
    int gr1 = l0 + r1; if (gr1 >= R) gr1 = R - 1;
    const char* sA0h = reinterpret_cast<const char*>(AH + (size_t)gr0 * Dd) + q * 16;
    const char* sA1h = reinterpret_cast<const char*>(AH + (size_t)gr1 * Dd) + q * 16;
    const char* sA0l = reinterpret_cast<const char*>(AL + (size_t)gr0 * Dd) + q * 16;
    const char* sA1l = reinterpret_cast<const char*>(AL + (size_t)gr1 * Dd) + q * 16;
    const char* sB0h = reinterpret_cast<const char*>(WH + (size_t)r0 * Dd) + q * 16;
    const char* sB1h = reinterpret_cast<const char*>(WH + (size_t)r1 * Dd) + q * 16;
    const char* sB0l = reinterpret_cast<const char*>(WL + (size_t)r0 * Dd) + q * 16;
    const char* sB1l = reinterpret_cast<const char*>(WL + (size_t)r1 * Dd) + q * 16;
    uint32_t d0 = sb + r0 * STRIDE + q * 16;
    uint32_t d1 = sb + r1 * STRIDE + q * 16;

    auto FILL = [&](int s, int kc, int nc) {
        uint32_t stg = s * STAGEB;
        int ko = kc * 64;                                 // bytes in k
        size_t bo = (size_t)nc * 128 * Dd * 2 + ko;       // B chunk offset
        CP16(d0 + stg,             sA0h + ko);
        CP16(d1 + stg,             sA1h + ko);
        CP16(d0 + stg + TILEB,     sA0l + ko);
        CP16(d1 + stg + TILEB,     sA1l + ko);
        CP16(d0 + stg + 2 * TILEB, sB0h + bo);
        CP16(d1 + stg + 2 * TILEB, sB1h + bo);
        CP16(d0 + stg + 3 * TILEB, sB0l + bo);
        CP16(d1 + stg + 3 * TILEB, sB1l + bo);
    };

    int warp = tid >> 5, lane = tid & 31;
    int g = lane >> 2, t = lane & 3;
    int m0 = (warp >> 1) * 32;
    int wn = warp & 1;
    int n0w = wn * 64;

    float acc[2][8][4];
    float partial[4] = {0.f, 0.f, 0.f, 0.f};

    auto COMPUTE = [&](int st) {
        const char* cA  = smem + st * STAGEB;
        const char* cAl = cA + TILEB;
        const char* cB  = cA + 2 * TILEB;
        const char* cBl = cA + 3 * TILEB;
        #pragma unroll
        for (int kk = 0; kk < BK; kk += 16) {
            uint32_t ah[2][4], al[2][4];
            #pragma unroll
            for (int sm = 0; sm < 2; sm++) {
                int o = (m0 + sm * 16 + g) * STRIDE + (kk + 2 * t) * 2;
                ah[sm][0] = *reinterpret_cast<const uint32_t*>(cA + o);
                ah[sm][1] = *reinterpret_cast<const uint32_t*>(cA + o + 8 * STRIDE);
                ah[sm][2] = *reinterpret_cast<const uint32_t*>(cA + o + 16);
                ah[sm][3] = *reinterpret_cast<const uint32_t*>(cA + o + 8 * STRIDE + 16);
                al[sm][0] = *reinterpret_cast<const uint32_t*>(cAl + o);
                al[sm][1] = *reinterpret_cast<const uint32_t*>(cAl + o + 8 * STRIDE);
                al[sm][2] = *reinterpret_cast<const uint32_t*>(cAl + o + 16);
                al[sm][3] = *reinterpret_cast<const uint32_t*>(cAl + o + 8 * STRIDE + 16);
            }
            #pragma unroll
            for (int ns = 0; ns < 8; ns++) {
                int o = (n0w + ns * 8 + g) * STRIDE + (kk + 2 * t) * 2;
                uint32_t bh0 = *reinterpret_cast<const uint32_t*>(cB + o);
                uint32_t bh1 = *reinterpret_cast<const uint32_t*>(cB + o + 16);
                uint32_t bl0 = *reinterpret_cast<const uint32_t*>(cBl + o);
                uint32_t bl1 = *reinterpret_cast<const uint32_t*>(cBl + o + 16);
                #pragma unroll
                for (int sm = 0; sm < 2; sm++) {
                    mma_bf16(acc[sm][ns], ah[sm], bh0, bh1);   // hi*hi
                    mma_bf16(acc[sm][ns], al[sm], bh0, bh1);   // lo*hi
                    mma_bf16(acc[sm][ns], ah[sm], bl0, bl1);   // hi*lo
                }
            }
        }
    };

    for (int nc = 0; nc < 6; nc++) {
        #pragma unroll
        for (int sm = 0; sm < 2; sm++)
            #pragma unroll
            for (int ns = 0; ns < 8; ns++)
                #pragma unroll
                for (int j = 0; j < 4; j++) acc[sm][ns][j] = 0.f;

        FILL(0, 0, nc); CP_COMMIT();
        FILL(1, 1, nc); CP_COMMIT();
        FILL(2, 2, nc); CP_COMMIT();

        for (int kc = 0; kc < 24; kc++) {
            CP_WAIT2();
            __syncthreads();
            COMPUTE(kc & 3);
            if (kc < 21) FILL((kc + 3) & 3, kc + 3, nc);
            CP_COMMIT();
        }

        // fused epilogue: tanh(acc + b) * v -> per-row partials
        #pragma unroll
        for (int sm = 0; sm < 2; sm++)
            #pragma unroll
            for (int ns = 0; ns < 8; ns++) {
                int col = nc * 128 + n0w + ns * 8 + 2 * t;
                float bb0 = __ldg(&bvec[col]), bb1 = __ldg(&bvec[col + 1]);
                float vv0 = __ldg(&vvec[col]), vv1 = __ldg(&vvec[col + 1]);
                partial[sm * 2 + 0] += tanh_f(acc[sm][ns][0] + bb0) * vv0
                                     + tanh_f(acc[sm][ns][1] + bb1) * vv1;
                partial[sm * 2 + 1] += tanh_f(acc[sm][ns][2] + bb0) * vv0
                                     + tanh_f(acc[sm][ns][3] + bb1) * vv1;
            }
        __syncthreads();   // all warps done with stages before next-nc refill
    }

    #pragma unroll
    for (int j = 0; j < 4; j++) {
        partial[j] += __shfl_xor_sync(0xffffffffu, partial[j], 1);
        partial[j] += __shfl_xor_sync(0xffffffffu, partial[j], 2);
    }
    float* red = reinterpret_cast<float*>(smem + NST * STAGEB);
    if (t == 0) {
        red[wn * 128 + m0 + g]      = partial[0];
        red[wn * 128 + m0 + 8 + g]  = partial[1];
        red[wn * 128 + m0 + 16 + g] = partial[2];
        red[wn * 128 + m0 + 24 + g] = partial[3];
    }
    __syncthreads();
    if (tid < 128) {
        int r = l0 + tid;
        if (r < R) {
            float val = red[tid] + red[128 + tid] + vbp[0];
            int oi = COMPACT ? g_rowmap[r] : r;
            outp[oi] = val;
        }
    }
}

// ---------------------------------------------------------------------------
// Masked softmax pooling; also emits bf16 hi/lo split of emb
// ---------------------------------------------------------------------------
__global__ __launch_bounds__(256) void k_pool(const float* __restrict__ x,
                                              const int* __restrict__ fs,
                                              const int* __restrict__ ssp)
{
    int p   = blockIdx.y;
    int sgi = blockIdx.x;
    int f = fs[p], s2 = ssp[p];
    int lo = sgi ? f + 1 : 1;
    int hi = sgi ? s2 : f;
    int cnt = hi - lo;

    __shared__ float w[160];
    __shared__ float red[256];
    int tid = threadIdx.x;

    const float* sc = g_scores + p * Ll + lo;

    float lm = -1e30f;
    for (int i = tid; i < cnt; i += 256) lm = fmaxf(lm, sc[i]);
    red[tid] = lm; __syncthreads();
    for (int o = 128; o > 0; o >>= 1) {
        if (tid < o) red[tid] = fmaxf(red[tid], red[tid + o]);
        __syncthreads();
    }
    float smax = red[0];
    __syncthreads();

    float le = 0.f;
    for (int i = tid; i < cnt; i += 256) {
        float e = __expf(sc[i] - smax);
        w[i] = e;
        le += e;
    }
    red[tid] = le; __syncthreads();
    for (int o = 128; o > 0; o >>= 1) {
        if (tid < o) red[tid] += red[tid + o];
        __syncthreads();
    }
    float inv = 1.0f / red[0];
    __syncthreads();

    float e0 = 0.f, e1 = 0.f, e2 = 0.f;
    const float* xr = x + ((size_t)p * Ll + lo) * Dd;
    for (int i = 0; i < cnt; i++) {
        float wl = w[i] * inv;
        const float* row = xr + (size_t)i * Dd;
        e0 += wl * row[tid];
        e1 += wl * row[tid + 256];
        e2 += wl * row[tid + 512];
    }
    int rowi = 2 * p + sgi;
    float* er = g_emb + (size_t)rowi * Dd;
    er[tid]       = e0;
    er[tid + 256] = e1;
    er[tid + 512] = e2;
    #pragma unroll
    for (int j = 0; j < 3; j++) {
        float e = j == 0 ? e0 : (j == 1 ? e1 : e2);
        int d = tid + j * 256;
        __nv_bfloat16 h = __float2bfloat16(e);
        __nv_bfloat16 l = __float2bfloat16(e - __bfloat162float(h));
        g_Eh[(size_t)rowi * Dd + d] = h;
        g_El[(size_t)rowi * Dd + d] = l;
    }
}

// ---------------------------------------------------------------------------
// Segment softmax + weighted sum
// ---------------------------------------------------------------------------
__global__ void k_out2(float* __restrict__ out) {
    int seg = blockIdx.x;
    int tid = threadIdx.x;
    __shared__ int   mem[14];
    __shared__ float wv[14];

    if (tid == 0) {
        int c = 0;
        for (int idx = 0; idx < PP2; idx++) {
            int pp = idx >> 1, cc = idx & 1;
            int z = pp / 56, r = pp % 56, j = r / 7, m = r % 7;
            int k = m + (m >= j ? 1 : 0);
            int sg = z * 8 + (cc == 0 ? j : k);
            if (sg == seg && c < 14) mem[c++] = idx;
        }
        float mx = -1e30f;
        for (int i = 0; i < 14; i++) mx = fmaxf(mx, g_sc[mem[i]]);
        float den = 0.f;
        for (int i = 0; i < 14; i++) {
            float e = __expf(g_sc[mem[i]] - mx);
            wv[i] = e;
            den += e;
        }
        float inv = 1.f / den;
        for (int i = 0; i < 14; i++) wv[i] *= inv;
    }
    __syncthreads();

    for (int d = tid; d < Dd; d += 256) {
        float a = 0.f;
        #pragma unroll
        for (int i = 0; i < 14; i++)
            a += wv[i] * g_emb[(size_t)mem[i] * Dd + d];
        out[Pp * Dd + seg * Dd + d] = a;
    }
}

// ---------------------------------------------------------------------------
// Launch
// ---------------------------------------------------------------------------
extern "C" void kernel_launch(void* const* d_in, const int* in_sizes, int n_in,
                              void* d_out, int out_size) {
    const float* x   = (const float*)d_in[0];
    const int*   fs  = (const int*)  d_in[1];
    const int*   ss  = (const int*)  d_in[2];
    const float* W1  = (const float*)d_in[3];
    const float* b1  = (const float*)d_in[4];
    const float* v1  = (const float*)d_in[5];
    const float* vb1 = (const float*)d_in[6];
    const float* W2  = (const float*)d_in[7];
    const float* b2  = (const float*)d_in[8];
    const float* v2  = (const float*)d_in[9];
    const float* vb2 = (const float*)d_in[10];
    float* out = (float*)d_out;

    static bool attr_done = false;
    if (!attr_done) {
        cudaFuncSetAttribute(k_gemm<true>,
            cudaFuncAttributeMaxDynamicSharedMemorySize, SMEM_TOT);
        cudaFuncSetAttribute(k_gemm<false>,
            cudaFuncAttributeMaxDynamicSharedMemorySize, SMEM_TOT);
        attr_done = true;
    }

    k_copy<<<(Pp * Dd + 255) / 256, 256>>>(x, out);
    k_convW<<<dim3(12, 12, 2), 256>>>(W1, W2);
    k_offsets<<<1, 256>>>(ss);
    k_convA<<<dim3(Ll, Pp), 192>>>(x, ss);

    k_gemm<true><<<dim3((RMAX + 127) / 128, 1), 256, SMEM_TOT>>>(b1, v1, vb1);

    k_pool<<<dim3(2, Pp), 256>>>(x, fs, ss);

    k_gemm<false><<<dim3(4, 1), 256, SMEM_TOT>>>(b2, v2, vb2);

    k_out2<<<Bb * Ss, 256>>>(out);
}

// round 5
// speedup vs baseline: 4.9771x; 1.4541x over previous
#include <cuda_runtime.h>
#include <cuda_bf16.h>
#include <cstdint>
#include <math.h>

#define Bb   4
#define Ss   8
#define Ll   350
#define Dd   768
#define Pp   224
#define PP2  448
#define RMAX (Pp * 300)        // second_sep < 300 strictly

// ---------------------------------------------------------------------------
// Scratch (static device globals; no allocation allowed)
// ---------------------------------------------------------------------------
__device__ float g_scores[Pp * Ll];
__device__ float g_emb[PP2 * Dd];
__device__ float g_sc[PP2];
__device__ int   g_poff[Pp + 1];
__device__ int   g_rowmap[RMAX];
// Pre-split operands (bf16 hi/lo), all [row][k] with k contiguous
__device__ __nv_bfloat16 g_Ah[RMAX * Dd];
__device__ __nv_bfloat16 g_Al[RMAX * Dd];
__device__ __nv_bfloat16 g_Eh[PP2 * Dd];
__device__ __nv_bfloat16 g_El[PP2 * Dd];
__device__ __nv_bfloat16 g_W1h[Dd * Dd];
__device__ __nv_bfloat16 g_W1l[Dd * Dd];
__device__ __nv_bfloat16 g_W2h[Dd * Dd];
__device__ __nv_bfloat16 g_W2l[Dd * Dd];

__device__ __forceinline__ uint32_t smem_u32(const void* p) {
    uint32_t a;
    asm("{ .reg .u64 t; cvta.to.shared.u64 t, %1; cvt.u32.u64 %0, t; }"
        : "=r"(a) : "l"(p));
    return a;
}

__device__ __forceinline__ uint32_t pack2(__nv_bfloat16 a, __nv_bfloat16 b) {
    return (uint32_t)__bfloat16_as_ushort(a) | ((uint32_t)__bfloat16_as_ushort(b) << 16);
}

__device__ __forceinline__ float tanh_f(float x) {
    x = fminf(15.f, fmaxf(-15.f, x));
    float e = __expf(2.f * x);
    return (e - 1.f) / (e + 1.f);
}

__device__ __forceinline__ void mma_bf16(float* c, const uint32_t* a,
                                         uint32_t b0, uint32_t b1) {
    asm volatile(
        "mma.sync.aligned.m16n8k16.row.col.f32.bf16.bf16.f32 "
        "{%0,%1,%2,%3}, {%4,%5,%6,%7}, {%8,%9}, {%0,%1,%2,%3};"
        : "+f"(c[0]), "+f"(c[1]), "+f"(c[2]), "+f"(c[3])
        : "r"(a[0]), "r"(a[1]), "r"(a[2]), "r"(a[3]), "r"(b0), "r"(b1));
}

#define LDSM4(r, a) \
    asm volatile("ldmatrix.sync.aligned.m8n8.x4.shared.b16 {%0,%1,%2,%3}, [%4];" \
        : "=r"((r)[0]), "=r"((r)[1]), "=r"((r)[2]), "=r"((r)[3]) : "r"(a))

#define CP16(dst, src) \
    asm volatile("cp.async.cg.shared.global [%0], [%1], 16;" \
                 :: "r"(dst), "l"(src) : "memory")
#define CP_COMMIT() asm volatile("cp.async.commit_group;" ::: "memory")
#define CP_WAIT2()  asm volatile("cp.async.wait_group 2;"  ::: "memory")

// ---------------------------------------------------------------------------
// Kernel 0: pair_embeddings = all_output[:, 0, :]
// ---------------------------------------------------------------------------
__global__ void k_copy(const float* __restrict__ x, float* __restrict__ out) {
    int i = blockIdx.x * 256 + threadIdx.x;
    if (i < Pp * Dd) {
        int p = i / Dd, d = i - p * Dd;
        out[i] = x[(size_t)p * Ll * Dd + d];
    }
}

// ---------------------------------------------------------------------------
// Zero atomic-accumulation targets
// ---------------------------------------------------------------------------
__global__ void k_zero() {
    int i = blockIdx.x * 256 + threadIdx.x;
    if (i < Pp * Ll) g_scores[i] = 0.f;
    if (i < PP2)     g_sc[i]     = 0.f;
}

// ---------------------------------------------------------------------------
// Prefix offsets of second_sep (compacted row layout)
// ---------------------------------------------------------------------------
__global__ void k_offsets(const int* __restrict__ ss) {
    __shared__ int s[Pp];
    int t = threadIdx.x;
    if (t < Pp) s[t] = ss[t];
    __syncthreads();
    if (t == 0) {
        int a = 0;
        for (int p = 0; p < Pp; p++) { int v = s[p]; s[p] = a; a += v; }
        g_poff[Pp] = a;
    }
    __syncthreads();
    if (t < Pp) g_poff[t] = s[t];
}

// ---------------------------------------------------------------------------
// Compact + split A: rows (p, l<ss[p]) -> g_Ah/g_Al, and row map
// ---------------------------------------------------------------------------
__global__ __launch_bounds__(192) void k_convA(const float* __restrict__ x,
                                               const int* __restrict__ ss) {
    int l = blockIdx.x, p = blockIdx.y;
    if (l >= ss[p]) return;
    int r = g_poff[p] + l;
    int tid = threadIdx.x;
    if (tid == 0) g_rowmap[r] = p * Ll + l;
    float4 v = *reinterpret_cast<const float4*>(
        x + ((size_t)p * Ll + l) * Dd + tid * 4);
    __nv_bfloat16 hx = __float2bfloat16(v.x), hy = __float2bfloat16(v.y);
    __nv_bfloat16 hz = __float2bfloat16(v.z), hw = __float2bfloat16(v.w);
    __nv_bfloat16 lx = __float2bfloat16(v.x - __bfloat162float(hx));
    __nv_bfloat16 ly = __float2bfloat16(v.y - __bfloat162float(hy));
    __nv_bfloat16 lz = __float2bfloat16(v.z - __bfloat162float(hz));
    __nv_bfloat16 lw = __float2bfloat16(v.w - __bfloat162float(hw));
    size_t off = ((size_t)r * Dd + tid * 4) * 2;
    *reinterpret_cast<uint2*>(reinterpret_cast<char*>(g_Ah) + off) =
        make_uint2(pack2(hx, hy), pack2(hz, hw));
    *reinterpret_cast<uint2*>(reinterpret_cast<char*>(g_Al) + off) =
        make_uint2(pack2(lx, ly), pack2(lz, lw));
}

// ---------------------------------------------------------------------------
// Weight prep: W[k][n] -> WT[n][k], split fp32 -> bf16 hi + lo
// ---------------------------------------------------------------------------
__global__ __launch_bounds__(256) void k_convW(const float* __restrict__ W1,
                                               const float* __restrict__ W2) {
    __shared__ float s[64][65];
    int k0 = blockIdx.x * 64, n0 = blockIdx.y * 64;
    const float* W = blockIdx.z ? W2 : W1;
    __nv_bfloat16* OH = blockIdx.z ? g_W2h : g_W1h;
    __nv_bfloat16* OL = blockIdx.z ? g_W2l : g_W1l;
    int tid = threadIdx.x;
    int nl = tid & 63, kl = tid >> 6;
    #pragma unroll
    for (int j = 0; j < 16; j++)
        s[kl + j * 4][nl] = W[(size_t)(k0 + kl + j * 4) * Dd + n0 + nl];
    __syncthreads();
    int q = tid & 31, nr = tid >> 5;
    #pragma unroll
    for (int j = 0; j < 8; j++) {
        int n = nr + j * 8;
        float x0 = s[2 * q][n], x1 = s[2 * q + 1][n];
        __nv_bfloat16 h0 = __float2bfloat16(x0);
        __nv_bfloat16 h1 = __float2bfloat16(x1);
        __nv_bfloat16 l0 = __float2bfloat16(x0 - __bfloat162float(h0));
        __nv_bfloat16 l1 = __float2bfloat16(x1 - __bfloat162float(h1));
        size_t off = (size_t)(n0 + n) * Dd + k0 + 2 * q;
        *reinterpret_cast<uint32_t*>(reinterpret_cast<char*>(OH) + off * 2) = pack2(h0, h1);
        *reinterpret_cast<uint32_t*>(reinterpret_cast<char*>(OL) + off * 2) = pack2(l0, l1);
    }
}

// ---------------------------------------------------------------------------
// Fused HMMA GEMM, cp.async 4-stage pipeline, ldmatrix fragments.
// grid = (row tiles, 6 n-chunks). CTA: 128 rows x 128 N, K=768 in BK=32
// stages. Per-row partials of tanh(acc+b)*v are atomicAdd'ed into the
// output (tanh is elementwise in n; bias vb cancels in downstream softmax).
// ---------------------------------------------------------------------------
#define BK      32
#define STRIDE  80
#define TILEB   10240
#define STAGEB  40960
#define NST     4
#define SMEM_TOT (NST * STAGEB + 1024)

template <bool COMPACT>
__global__ __launch_bounds__(256, 1) void k_gemm(
    const float* __restrict__ bvec, const float* __restrict__ vvec)
{
    extern __shared__ char smem[];
    int tid = threadIdx.x;
    int l0 = blockIdx.x * 128;
    int nc = blockIdx.y;

    int R = COMPACT ? g_poff[Pp] : PP2;
    if (l0 >= R) return;

    const __nv_bfloat16* AH = COMPACT ? g_Ah : g_Eh;
    const __nv_bfloat16* AL = COMPACT ? g_Al : g_El;
    const __nv_bfloat16* WH = COMPACT ? g_W1h : g_W2h;
    const __nv_bfloat16* WL = COMPACT ? g_W1l : g_W2l;
    float* outp = COMPACT ? g_scores : g_sc;

    uint32_t sb = smem_u32(smem);

    // fixed per-thread copy lanes: rows r0,r1; 16B chunk q
    int q = tid & 3, r0 = tid >> 2, r1 = r0 + 64;
    int gr0 = l0 + r0; if (gr0 >= R) gr0 = R - 1;
    int gr1 = l0 + r1; if (gr1 >= R) gr1 = R - 1;
    const char* sA0h = reinterpret_cast<const char*>(AH + (size_t)gr0 * Dd) + q * 16;
    const char* sA1h = reinterpret_cast<const char*>(AH + (size_t)gr1 * Dd) + q * 16;
    const char* sA0l = reinterpret_cast<const char*>(AL + (size_t)gr0 * Dd) + q * 16;
    const char* sA1l = reinterpret_cast<const char*>(AL + (size_t)gr1 * Dd) + q * 16;
    const char* sB0h = reinterpret_cast<const char*>(WH + (size_t)(nc * 128 + r0) * Dd) + q * 16;
    const char* sB1h = reinterpret_cast<const char*>(WH + (size_t)(nc * 128 + r1) * Dd) + q * 16;
    const char* sB0l = reinterpret_cast<const char*>(WL + (size_t)(nc * 128 + r0) * Dd) + q * 16;
    const char* sB1l = reinterpret_cast<const char*>(WL + (size_t)(nc * 128 + r1) * Dd) + q * 16;
    uint32_t d0 = sb + r0 * STRIDE + q * 16;
    uint32_t d1 = sb + r1 * STRIDE + q * 16;

    auto FILL = [&](int s, int kc) {
        uint32_t stg = s * STAGEB;
        int ko = kc * 64;                                 // bytes along k
        CP16(d0 + stg,             sA0h + ko);
        CP16(d1 + stg,             sA1h + ko);
        CP16(d0 + stg + TILEB,     sA0l + ko);
        CP16(d1 + stg + TILEB,     sA1l + ko);
        CP16(d0 + stg + 2 * TILEB, sB0h + ko);
        CP16(d1 + stg + 2 * TILEB, sB1h + ko);
        CP16(d0 + stg + 3 * TILEB, sB0l + ko);
        CP16(d1 + stg + 3 * TILEB, sB1l + ko);
    };

    int warp = tid >> 5, lane = tid & 31;
    int g = lane >> 2, t = lane & 3;
    int m0 = (warp >> 1) * 32;
    int wn = warp & 1;
    int n0w = wn * 64;

    // ldmatrix lane offsets (within a tile, bytes)
    int aoff = ((lane & 7) + ((lane >> 3) & 1) * 8) * STRIDE + (lane >> 4) * 16;
    int boff = ((lane >> 4) * 8 + (lane & 7)) * STRIDE + ((lane >> 3) & 1) * 16;

    float acc[2][8][4];
    #pragma unroll
    for (int sm = 0; sm < 2; sm++)
        #pragma unroll
        for (int ns = 0; ns < 8; ns++)
            #pragma unroll
            for (int j = 0; j < 4; j++) acc[sm][ns][j] = 0.f;

    auto COMPUTE = [&](int st) {
        uint32_t base = sb + st * STAGEB;
        #pragma unroll
        for (int kk = 0; kk < BK; kk += 16) {
            uint32_t ah[2][4], al[2][4];
            #pragma unroll
            for (int sm = 0; sm < 2; sm++) {
                uint32_t ad = base + (m0 + sm * 16) * STRIDE + aoff + kk * 2;
                LDSM4(ah[sm], ad);
                LDSM4(al[sm], ad + TILEB);
            }
            #pragma unroll
            for (int ns2 = 0; ns2 < 4; ns2++) {
                uint32_t bh[4], bl[4];
                uint32_t bd = base + 2 * TILEB + (n0w + ns2 * 16) * STRIDE + boff + kk * 2;
                LDSM4(bh, bd);
                LDSM4(bl, bd + TILEB);
                #pragma unroll
                for (int sm = 0; sm < 2; sm++) {
                    mma_bf16(acc[sm][2 * ns2],     ah[sm], bh[0], bh[1]);
                    mma_bf16(acc[sm][2 * ns2],     al[sm], bh[0], bh[1]);
                    mma_bf16(acc[sm][2 * ns2],     ah[sm], bl[0], bl[1]);
                    mma_bf16(acc[sm][2 * ns2 + 1], ah[sm], bh[2], bh[3]);
                    mma_bf16(acc[sm][2 * ns2 + 1], al[sm], bh[2], bh[3]);
                    mma_bf16(acc[sm][2 * ns2 + 1], ah[sm], bl[2], bl[3]);
                }
            }
        }
    };

    FILL(0, 0); CP_COMMIT();
    FILL(1, 1); CP_COMMIT();
    FILL(2, 2); CP_COMMIT();

    for (int kc = 0; kc < 24; kc++) {
        CP_WAIT2();
        __syncthreads();
        COMPUTE(kc & 3);
        if (kc < 21) FILL((kc + 3) & 3, kc + 3);
        CP_COMMIT();
    }

    // fused epilogue: tanh(acc + b) * v -> per-row partials (this n-chunk)
    float partial[4] = {0.f, 0.f, 0.f, 0.f};
    #pragma unroll
    for (int sm = 0; sm < 2; sm++)
        #pragma unroll
        for (int ns = 0; ns < 8; ns++) {
            int col = nc * 128 + n0w + ns * 8 + 2 * t;
            float bb0 = __ldg(&bvec[col]), bb1 = __ldg(&bvec[col + 1]);
            float vv0 = __ldg(&vvec[col]), vv1 = __ldg(&vvec[col + 1]);
            partial[sm * 2 + 0] += tanh_f(acc[sm][ns][0] + bb0) * vv0
                                 + tanh_f(acc[sm][ns][1] + bb1) * vv1;
            partial[sm * 2 + 1] += tanh_f(acc[sm][ns][2] + bb0) * vv0
                                 + tanh_f(acc[sm][ns][3] + bb1) * vv1;
        }

    #pragma unroll
    for (int j = 0; j < 4; j++) {
        partial[j] += __shfl_xor_sync(0xffffffffu, partial[j], 1);
        partial[j] += __shfl_xor_sync(0xffffffffu, partial[j], 2);
    }
    float* red = reinterpret_cast<float*>(smem + NST * STAGEB);
    __syncthreads();
    if (t == 0) {
        red[wn * 128 + m0 + g]      = partial[0];
        red[wn * 128 + m0 + 8 + g]  = partial[1];
        red[wn * 128 + m0 + 16 + g] = partial[2];
        red[wn * 128 + m0 + 24 + g] = partial[3];
    }
    __syncthreads();
    if (tid < 128) {
        int r = l0 + tid;
        if (r < R) {
            float val = red[tid] + red[128 + tid];
            int oi = COMPACT ? g_rowmap[r] : r;
            atomicAdd(&outp[oi], val);
        }
    }
}

// ---------------------------------------------------------------------------
// Masked softmax pooling; also emits bf16 hi/lo split of emb
// ---------------------------------------------------------------------------
__global__ __launch_bounds__(256) void k_pool(const float* __restrict__ x,
                                              const int* __restrict__ fs,
                                              const int* __restrict__ ssp)
{
    int p   = blockIdx.y;
    int sgi = blockIdx.x;
    int f = fs[p], s2 = ssp[p];
    int lo = sgi ? f + 1 : 1;
    int hi = sgi ? s2 : f;
    int cnt = hi - lo;

    __shared__ float w[160];
    __shared__ float red[256];
    int tid = threadIdx.x;

    const float* sc = g_scores + p * Ll + lo;

    float lm = -1e30f;
    for (int i = tid; i < cnt; i += 256) lm = fmaxf(lm, sc[i]);
    red[tid] = lm; __syncthreads();
    for (int o = 128; o > 0; o >>= 1) {
        if (tid < o) red[tid] = fmaxf(red[tid], red[tid + o]);
        __syncthreads();
    }
    float smax = red[0];
    __syncthreads();

    float le = 0.f;
    for (int i = tid; i < cnt; i += 256) {
        float e = __expf(sc[i] - smax);
        w[i] = e;
        le += e;
    }
    red[tid] = le; __syncthreads();
    for (int o = 128; o > 0; o >>= 1) {
        if (tid < o) red[tid] += red[tid + o];
        __syncthreads();
    }
    float inv = 1.0f / red[0];
    __syncthreads();

    float e0 = 0.f, e1 = 0.f, e2 = 0.f;
    const float* xr = x + ((size_t)p * Ll + lo) * Dd;
    for (int i = 0; i < cnt; i++) {
        float wl = w[i] * inv;
        const float* row = xr + (size_t)i * Dd;
        e0 += wl * row[tid];
        e1 += wl * row[tid + 256];
        e2 += wl * row[tid + 512];
    }
    int rowi = 2 * p + sgi;
    float* er = g_emb + (size_t)rowi * Dd;
    er[tid]       = e0;
    er[tid + 256] = e1;
    er[tid + 512] = e2;
    #pragma unroll
    for (int j = 0; j < 3; j++) {
        float e = j == 0 ? e0 : (j == 1 ? e1 : e2);
        int d = tid + j * 256;
        __nv_bfloat16 h = __float2bfloat16(e);
        __nv_bfloat16 l = __float2bfloat16(e - __bfloat162float(h));
        g_Eh[(size_t)rowi * Dd + d] = h;
        g_El[(size_t)rowi * Dd + d] = l;
    }
}

// ---------------------------------------------------------------------------
// Segment softmax + weighted sum
// ---------------------------------------------------------------------------
__global__ void k_out2(float* __restrict__ out) {
    int seg = blockIdx.x;
    int tid = threadIdx.x;
    __shared__ int   mem[14];
    __shared__ float wv[14];

    if (tid == 0) {
        int c = 0;
        for (int idx = 0; idx < PP2; idx++) {
            int pp = idx >> 1, cc = idx & 1;
            int z = pp / 56, r = pp % 56, j = r / 7, m = r % 7;
            int k = m + (m >= j ? 1 : 0);
            int sg = z * 8 + (cc == 0 ? j : k);
            if (sg == seg && c < 14) mem[c++] = idx;
        }
        float mx = -1e30f;
        for (int i = 0; i < 14; i++) mx = fmaxf(mx, g_sc[mem[i]]);
        float den = 0.f;
        for (int i = 0; i < 14; i++) {
            float e = __expf(g_sc[mem[i]] - mx);
            wv[i] = e;
            den += e;
        }
        float inv = 1.f / den;
        for (int i = 0; i < 14; i++) wv[i] *= inv;
    }
    __syncthreads();

    for (int d = tid; d < Dd; d += 256) {
        float a = 0.f;
        #pragma unroll
        for (int i = 0; i < 14; i++)
            a += wv[i] * g_emb[(size_t)mem[i] * Dd + d];
        out[Pp * Dd + seg * Dd + d] = a;
    }
}

// ---------------------------------------------------------------------------
// Launch
// ---------------------------------------------------------------------------
extern "C" void kernel_launch(void* const* d_in, const int* in_sizes, int n_in,
                              void* d_out, int out_size) {
    const float* x   = (const float*)d_in[0];
    const int*   fs  = (const int*)  d_in[1];
    const int*   ss  = (const int*)  d_in[2];
    const float* W1  = (const float*)d_in[3];
    const float* b1  = (const float*)d_in[4];
    const float* v1  = (const float*)d_in[5];
    const float* W2  = (const float*)d_in[7];
    const float* b2  = (const float*)d_in[8];
    const float* v2  = (const float*)d_in[9];
    float* out = (float*)d_out;

    static bool attr_done = false;
    if (!attr_done) {
        cudaFuncSetAttribute(k_gemm<true>,
            cudaFuncAttributeMaxDynamicSharedMemorySize, SMEM_TOT);
        cudaFuncSetAttribute(k_gemm<false>,
            cudaFuncAttributeMaxDynamicSharedMemorySize, SMEM_TOT);
        attr_done = true;
    }

    k_copy<<<(Pp * Dd + 255) / 256, 256>>>(x, out);
    k_zero<<<(Pp * Ll + 255) / 256, 256>>>();
    k_convW<<<dim3(12, 12, 2), 256>>>(W1, W2);
    k_offsets<<<1, 256>>>(ss);
    k_convA<<<dim3(Ll, Pp), 192>>>(x, ss);

    k_gemm<true><<<dim3((RMAX + 127) / 128, 6), 256, SMEM_TOT>>>(b1, v1);

    k_pool<<<dim3(2, Pp), 256>>>(x, fs, ss);

    k_gemm<false><<<dim3(4, 6), 256, SMEM_TOT>>>(b2, v2);

    k_out2<<<Bb * Ss, 256>>>(out);
}

// round 6
// speedup vs baseline: 5.8948x; 1.1844x over previous
#include <cuda_runtime.h>
#include <cuda_fp16.h>
#include <cstdint>
#include <math.h>

#define Bb   4
#define Ss   8
#define Ll   350
#define Dd   768
#define Pp   224
#define PP2  448
#define RMAX (Pp * 300)        // second_sep < 300 strictly

// ---------------------------------------------------------------------------
// Scratch (static device globals; no allocation allowed)
// ---------------------------------------------------------------------------
__device__ float g_scores[Pp * Ll];
__device__ float g_emb[PP2 * Dd];
__device__ float g_sc[PP2];
__device__ int   g_poff[Pp + 1];
__device__ int   g_rowmap[RMAX];
// Pre-split operands (fp16 hi/lo for A-side; fp16 hi only for W-side)
__device__ __half g_Ah[RMAX * Dd];
__device__ __half g_Al[RMAX * Dd];
__device__ __half g_Eh[PP2 * Dd];
__device__ __half g_El[PP2 * Dd];
__device__ __half g_W1h[Dd * Dd];
__device__ __half g_W2h[Dd * Dd];

__device__ __forceinline__ uint32_t smem_u32(const void* p) {
    uint32_t a;
    asm("{ .reg .u64 t; cvta.to.shared.u64 t, %1; cvt.u32.u64 %0, t; }"
        : "=r"(a) : "l"(p));
    return a;
}

__device__ __forceinline__ uint32_t pack2h(__half a, __half b) {
    return (uint32_t)__half_as_ushort(a) | ((uint32_t)__half_as_ushort(b) << 16);
}

__device__ __forceinline__ float tanh_f(float x) {
    x = fminf(15.f, fmaxf(-15.f, x));
    float e = __expf(2.f * x);
    return (e - 1.f) / (e + 1.f);
}

__device__ __forceinline__ void mma_fp16(float* c, const uint32_t* a,
                                         uint32_t b0, uint32_t b1) {
    asm volatile(
        "mma.sync.aligned.m16n8k16.row.col.f32.f16.f16.f32 "
        "{%0,%1,%2,%3}, {%4,%5,%6,%7}, {%8,%9}, {%0,%1,%2,%3};"
        : "+f"(c[0]), "+f"(c[1]), "+f"(c[2]), "+f"(c[3])
        : "r"(a[0]), "r"(a[1]), "r"(a[2]), "r"(a[3]), "r"(b0), "r"(b1));
}

#define LDSM4(r, a) \
    asm volatile("ldmatrix.sync.aligned.m8n8.x4.shared.b16 {%0,%1,%2,%3}, [%4];" \
        : "=r"((r)[0]), "=r"((r)[1]), "=r"((r)[2]), "=r"((r)[3]) : "r"(a))

#define CP16(dst, src) \
    asm volatile("cp.async.cg.shared.global [%0], [%1], 16;" \
                 :: "r"(dst), "l"(src) : "memory")
#define CP_COMMIT() asm volatile("cp.async.commit_group;" ::: "memory")
#define CP_WAIT2()  asm volatile("cp.async.wait_group 2;"  ::: "memory")

// ---------------------------------------------------------------------------
// Kernel 0: pair_embeddings = all_output[:, 0, :]
// ---------------------------------------------------------------------------
__global__ void k_copy(const float* __restrict__ x, float* __restrict__ out) {
    int i = blockIdx.x * 256 + threadIdx.x;
    if (i < Pp * Dd) {
        int p = i / Dd, d = i - p * Dd;
        out[i] = x[(size_t)p * Ll * Dd + d];
    }
}

// ---------------------------------------------------------------------------
// Zero atomic-accumulation targets
// ---------------------------------------------------------------------------
__global__ void k_zero() {
    int i = blockIdx.x * 256 + threadIdx.x;
    if (i < Pp * Ll) g_scores[i] = 0.f;
    if (i < PP2)     g_sc[i]     = 0.f;
}

// ---------------------------------------------------------------------------
// Prefix offsets of second_sep (compacted row layout)
// ---------------------------------------------------------------------------
__global__ void k_offsets(const int* __restrict__ ss) {
    __shared__ int s[Pp];
    int t = threadIdx.x;
    if (t < Pp) s[t] = ss[t];
    __syncthreads();
    if (t == 0) {
        int a = 0;
        for (int p = 0; p < Pp; p++) { int v = s[p]; s[p] = a; a += v; }
        g_poff[Pp] = a;
    }
    __syncthreads();
    if (t < Pp) g_poff[t] = s[t];
}

// ---------------------------------------------------------------------------
// Compact + split A: rows (p, l<ss[p]) -> g_Ah/g_Al (fp16 hi/lo), row map
// ---------------------------------------------------------------------------
__global__ __launch_bounds__(192) void k_convA(const float* __restrict__ x,
                                               const int* __restrict__ ss) {
    int l = blockIdx.x, p = blockIdx.y;
    if (l >= ss[p]) return;
    int r = g_poff[p] + l;
    int tid = threadIdx.x;
    if (tid == 0) g_rowmap[r] = p * Ll + l;
    float4 v = *reinterpret_cast<const float4*>(
        x + ((size_t)p * Ll + l) * Dd + tid * 4);
    __half hx = __float2half(v.x), hy = __float2half(v.y);
    __half hz = __float2half(v.z), hw = __float2half(v.w);
    __half lx = __float2half(v.x - __half2float(hx));
    __half ly = __float2half(v.y - __half2float(hy));
    __half lz = __float2half(v.z - __half2float(hz));
    __half lw = __float2half(v.w - __half2float(hw));
    size_t off = ((size_t)r * Dd + tid * 4) * 2;
    *reinterpret_cast<uint2*>(reinterpret_cast<char*>(g_Ah) + off) =
        make_uint2(pack2h(hx, hy), pack2h(hz, hw));
    *reinterpret_cast<uint2*>(reinterpret_cast<char*>(g_Al) + off) =
        make_uint2(pack2h(lx, ly), pack2h(lz, lw));
}

// ---------------------------------------------------------------------------
// Weight prep: W[k][n] -> WT[n][k], fp16 (hi only; B truncation error is
// within tolerance under the 2-term split)
// ---------------------------------------------------------------------------
__global__ __launch_bounds__(256) void k_convW(const float* __restrict__ W1,
                                               const float* __restrict__ W2) {
    __shared__ float s[64][65];
    int k0 = blockIdx.x * 64, n0 = blockIdx.y * 64;
    const float* W = blockIdx.z ? W2 : W1;
    __half* OH = blockIdx.z ? g_W2h : g_W1h;
    int tid = threadIdx.x;
    int nl = tid & 63, kl = tid >> 6;
    #pragma unroll
    for (int j = 0; j < 16; j++)
        s[kl + j * 4][nl] = W[(size_t)(k0 + kl + j * 4) * Dd + n0 + nl];
    __syncthreads();
    int q = tid & 31, nr = tid >> 5;
    #pragma unroll
    for (int j = 0; j < 8; j++) {
        int n = nr + j * 8;
        __half h0 = __float2half(s[2 * q][n]);
        __half h1 = __float2half(s[2 * q + 1][n]);
        size_t off = (size_t)(n0 + n) * Dd + k0 + 2 * q;
        *reinterpret_cast<uint32_t*>(reinterpret_cast<char*>(OH) + off * 2) = pack2h(h0, h1);
    }
}

// ---------------------------------------------------------------------------
// Fused HMMA GEMM (fp16 2-term split), cp.async 4-stage, ldmatrix fragments.
// grid = (row tiles, 6 n-chunks). CTA: 128 rows x 128 N, BK=32 stages.
// acc = Ah*Bh + Al*Bh. Per-row tanh(acc+b)*v partials atomicAdd'ed out.
// ---------------------------------------------------------------------------
#define BK      32
#define STRIDE  80
#define TILEB   10240
#define STAGEB  30720          // Ah | Al | Bh
#define NST     4
#define SMEM_TOT (NST * STAGEB + 1024)

template <bool COMPACT>
__global__ __launch_bounds__(256, 1) void k_gemm(
    const float* __restrict__ bvec, const float* __restrict__ vvec)
{
    extern __shared__ char smem[];
    int tid = threadIdx.x;
    int l0 = blockIdx.x * 128;
    int nc = blockIdx.y;

    int R = COMPACT ? g_poff[Pp] : PP2;
    if (l0 >= R) return;

    const __half* AH = COMPACT ? g_Ah : g_Eh;
    const __half* AL = COMPACT ? g_Al : g_El;
    const __half* WH = COMPACT ? g_W1h : g_W2h;
    float* outp = COMPACT ? g_scores : g_sc;

    uint32_t sb = smem_u32(smem);

    // fixed per-thread copy lanes: rows r0,r1; 16B chunk q
    int q = tid & 3, r0 = tid >> 2, r1 = r0 + 64;
    int gr0 = l0 + r0; if (gr0 >= R) gr0 = R - 1;
    int gr1 = l0 + r1; if (gr1 >= R) gr1 = R - 1;
    const char* sA0h = reinterpret_cast<const char*>(AH + (size_t)gr0 * Dd) + q * 16;
    const char* sA1h = reinterpret_cast<const char*>(AH + (size_t)gr1 * Dd) + q * 16;
    const char* sA0l = reinterpret_cast<const char*>(AL + (size_t)gr0 * Dd) + q * 16;
    const char* sA1l = reinterpret_cast<const char*>(AL + (size_t)gr1 * Dd) + q * 16;
    const char* sB0h = reinterpret_cast<const char*>(WH + (size_t)(nc * 128 + r0) * Dd) + q * 16;
    const char* sB1h = reinterpret_cast<const char*>(WH + (size_t)(nc * 128 + r1) * Dd) + q * 16;
    uint32_t d0 = sb + r0 * STRIDE + q * 16;
    uint32_t d1 = sb + r1 * STRIDE + q * 16;

    auto FILL = [&](int s, int kc) {
        uint32_t stg = s * STAGEB;
        int ko = kc * 64;                                 // bytes along k
        CP16(d0 + stg,             sA0h + ko);
        CP16(d1 + stg,             sA1h + ko);
        CP16(d0 + stg + TILEB,     sA0l + ko);
        CP16(d1 + stg + TILEB,     sA1l + ko);
        CP16(d0 + stg + 2 * TILEB, sB0h + ko);
        CP16(d1 + stg + 2 * TILEB, sB1h + ko);
    };

    int warp = tid >> 5, lane = tid & 31;
    int g = lane >> 2, t = lane & 3;
    int m0 = (warp >> 1) * 32;
    int wn = warp & 1;
    int n0w = wn * 64;

    // ldmatrix lane offsets (within a tile, bytes)
    int aoff = ((lane & 7) + ((lane >> 3) & 1) * 8) * STRIDE + (lane >> 4) * 16;
    int boff = ((lane >> 4) * 8 + (lane & 7)) * STRIDE + ((lane >> 3) & 1) * 16;

    float acc[2][8][4];
    #pragma unroll
    for (int sm = 0; sm < 2; sm++)
        #pragma unroll
        for (int ns = 0; ns < 8; ns++)
            #pragma unroll
            for (int j = 0; j < 4; j++) acc[sm][ns][j] = 0.f;

    auto COMPUTE = [&](int st) {
        uint32_t base = sb + st * STAGEB;
        #pragma unroll
        for (int kk = 0; kk < BK; kk += 16) {
            uint32_t ah[2][4], al[2][4];
            #pragma unroll
            for (int sm = 0; sm < 2; sm++) {
                uint32_t ad = base + (m0 + sm * 16) * STRIDE + aoff + kk * 2;
                LDSM4(ah[sm], ad);
                LDSM4(al[sm], ad + TILEB);
            }
            #pragma unroll
            for (int ns2 = 0; ns2 < 4; ns2++) {
                uint32_t bh[4];
                uint32_t bd = base + 2 * TILEB + (n0w + ns2 * 16) * STRIDE + boff + kk * 2;
                LDSM4(bh, bd);
                #pragma unroll
                for (int sm = 0; sm < 2; sm++) {
                    mma_fp16(acc[sm][2 * ns2],     ah[sm], bh[0], bh[1]);
                    mma_fp16(acc[sm][2 * ns2],     al[sm], bh[0], bh[1]);
                    mma_fp16(acc[sm][2 * ns2 + 1], ah[sm], bh[2], bh[3]);
                    mma_fp16(acc[sm][2 * ns2 + 1], al[sm], bh[2], bh[3]);
                }
            }
        }
    };

    FILL(0, 0); CP_COMMIT();
    FILL(1, 1); CP_COMMIT();
    FILL(2, 2); CP_COMMIT();

    for (int kc = 0; kc < 24; kc++) {
        CP_WAIT2();
        __syncthreads();
        COMPUTE(kc & 3);
        if (kc < 21) FILL((kc + 3) & 3, kc + 3);
        CP_COMMIT();
    }

    // fused epilogue: tanh(acc + b) * v -> per-row partials (this n-chunk)
    float partial[4] = {0.f, 0.f, 0.f, 0.f};
    #pragma unroll
    for (int sm = 0; sm < 2; sm++)
        #pragma unroll
        for (int ns = 0; ns < 8; ns++) {
            int col = nc * 128 + n0w + ns * 8 + 2 * t;
            float bb0 = __ldg(&bvec[col]), bb1 = __ldg(&bvec[col + 1]);
            float vv0 = __ldg(&vvec[col]), vv1 = __ldg(&vvec[col + 1]);
            partial[sm * 2 + 0] += tanh_f(acc[sm][ns][0] + bb0) * vv0
                                 + tanh_f(acc[sm][ns][1] + bb1) * vv1;
            partial[sm * 2 + 1] += tanh_f(acc[sm][ns][2] + bb0) * vv0
                                 + tanh_f(acc[sm][ns][3] + bb1) * vv1;
        }

    #pragma unroll
    for (int j = 0; j < 4; j++) {
        partial[j] += __shfl_xor_sync(0xffffffffu, partial[j], 1);
        partial[j] += __shfl_xor_sync(0xffffffffu, partial[j], 2);
    }
    float* red = reinterpret_cast<float*>(smem + NST * STAGEB);
    __syncthreads();
    if (t == 0) {
        red[wn * 128 + m0 + g]      = partial[0];
        red[wn * 128 + m0 + 8 + g]  = partial[1];
        red[wn * 128 + m0 + 16 + g] = partial[2];
        red[wn * 128 + m0 + 24 + g] = partial[3];
    }
    __syncthreads();
    if (tid < 128) {
        int r = l0 + tid;
        if (r < R) {
            float val = red[tid] + red[128 + tid];
            int oi = COMPACT ? g_rowmap[r] : r;
            atomicAdd(&outp[oi], val);
        }
    }
}

// ---------------------------------------------------------------------------
// Masked softmax pooling; emits fp16 hi/lo split of emb. Weighted-sum loop
// unrolled x4 for MLP (was 34% DRAM at MLP=3).
// ---------------------------------------------------------------------------
__global__ __launch_bounds__(256) void k_pool(const float* __restrict__ x,
                                              const int* __restrict__ fs,
                                              const int* __restrict__ ssp)
{
    int p   = blockIdx.y;
    int sgi = blockIdx.x;
    int f = fs[p], s2 = ssp[p];
    int lo = sgi ? f + 1 : 1;
    int hi = sgi ? s2 : f;
    int cnt = hi - lo;

    __shared__ float w[160];
    __shared__ float red[256];
    int tid = threadIdx.x;

    const float* sc = g_scores + p * Ll + lo;

    float lm = -1e30f;
    for (int i = tid; i < cnt; i += 256) lm = fmaxf(lm, sc[i]);
    red[tid] = lm; __syncthreads();
    for (int o = 128; o > 0; o >>= 1) {
        if (tid < o) red[tid] = fmaxf(red[tid], red[tid + o]);
        __syncthreads();
    }
    float smax = red[0];
    __syncthreads();

    float le = 0.f;
    for (int i = tid; i < cnt; i += 256) {
        float e = __expf(sc[i] - smax);
        w[i] = e;
        le += e;
    }
    red[tid] = le; __syncthreads();
    for (int o = 128; o > 0; o >>= 1) {
        if (tid < o) red[tid] += red[tid + o];
        __syncthreads();
    }
    float inv = 1.0f / red[0];
    __syncthreads();
    for (int i = tid; i < cnt; i += 256) w[i] *= inv;
    __syncthreads();

    float e0 = 0.f, e1 = 0.f, e2 = 0.f;
    const float* xr = x + ((size_t)p * Ll + lo) * Dd;
    int i = 0;
    for (; i + 4 <= cnt; i += 4) {
        const float* r0 = xr + (size_t)i * Dd;
        const float* r1 = r0 + Dd;
        const float* r2 = r1 + Dd;
        const float* r3 = r2 + Dd;
        float w0 = w[i], w1 = w[i + 1], w2 = w[i + 2], w3 = w[i + 3];
        e0 += w0 * r0[tid]       + w1 * r1[tid]       + w2 * r2[tid]       + w3 * r3[tid];
        e1 += w0 * r0[tid + 256] + w1 * r1[tid + 256] + w2 * r2[tid + 256] + w3 * r3[tid + 256];
        e2 += w0 * r0[tid + 512] + w1 * r1[tid + 512] + w2 * r2[tid + 512] + w3 * r3[tid + 512];
    }
    for (; i < cnt; i++) {
        float wl = w[i];
        const float* row = xr + (size_t)i * Dd;
        e0 += wl * row[tid];
        e1 += wl * row[tid + 256];
        e2 += wl * row[tid + 512];
    }
    int rowi = 2 * p + sgi;
    float* er = g_emb + (size_t)rowi * Dd;
    er[tid]       = e0;
    er[tid + 256] = e1;
    er[tid + 512] = e2;
    #pragma unroll
    for (int j = 0; j < 3; j++) {
        float e = j == 0 ? e0 : (j == 1 ? e1 : e2);
        int d = tid + j * 256;
        __half h = __float2half(e);
        __half l = __float2half(e - __half2float(h));
        g_Eh[(size_t)rowi * Dd + d] = h;
        g_El[(size_t)rowi * Dd + d] = l;
    }
}

// ---------------------------------------------------------------------------
// Segment softmax + weighted sum
// ---------------------------------------------------------------------------
__global__ void k_out2(float* __restrict__ out) {
    int seg = blockIdx.x;
    int tid = threadIdx.x;
    __shared__ int   mem[14];
    __shared__ float wv[14];

    if (tid == 0) {
        int c = 0;
        for (int idx = 0; idx < PP2; idx++) {
            int pp = idx >> 1, cc = idx & 1;
            int z = pp / 56, r = pp % 56, j = r / 7, m = r % 7;
            int k = m + (m >= j ? 1 : 0);
            int sg = z * 8 + (cc == 0 ? j : k);
            if (sg == seg && c < 14) mem[c++] = idx;
        }
        float mx = -1e30f;
        for (int i = 0; i < 14; i++) mx = fmaxf(mx, g_sc[mem[i]]);
        float den = 0.f;
        for (int i = 0; i < 14; i++) {
            float e = __expf(g_sc[mem[i]] - mx);
            wv[i] = e;
            den += e;
        }
        float inv = 1.f / den;
        for (int i = 0; i < 14; i++) wv[i] *= inv;
    }
    __syncthreads();

    for (int d = tid; d < Dd; d += 256) {
        float a = 0.f;
        #pragma unroll
        for (int i = 0; i < 14; i++)
            a += wv[i] * g_emb[(size_t)mem[i] * Dd + d];
        out[Pp * Dd + seg * Dd + d] = a;
    }
}

// ---------------------------------------------------------------------------
// Launch
// ---------------------------------------------------------------------------
extern "C" void kernel_launch(void* const* d_in, const int* in_sizes, int n_in,
                              void* d_out, int out_size) {
    const float* x   = (const float*)d_in[0];
    const int*   fs  = (const int*)  d_in[1];
    const int*   ss  = (const int*)  d_in[2];
    const float* W1  = (const float*)d_in[3];
    const float* b1  = (const float*)d_in[4];
    const float* v1  = (const float*)d_in[5];
    const float* W2  = (const float*)d_in[7];
    const float* b2  = (const float*)d_in[8];
    const float* v2  = (const float*)d_in[9];
    float* out = (float*)d_out;

    static bool attr_done = false;
    if (!attr_done) {
        cudaFuncSetAttribute(k_gemm<true>,
            cudaFuncAttributeMaxDynamicSharedMemorySize, SMEM_TOT);
        cudaFuncSetAttribute(k_gemm<false>,
            cudaFuncAttributeMaxDynamicSharedMemorySize, SMEM_TOT);
        attr_done = true;
    }

    k_copy<<<(Pp * Dd + 255) / 256, 256>>>(x, out);
    k_zero<<<(Pp * Ll + 255) / 256, 256>>>();
    k_convW<<<dim3(12, 12, 2), 256>>>(W1, W2);
    k_offsets<<<1, 256>>>(ss);
    k_convA<<<dim3(Ll, Pp), 192>>>(x, ss);

    k_gemm<true><<<dim3((RMAX + 127) / 128, 6), 256, SMEM_TOT>>>(b1, v1);

    k_pool<<<dim3(2, Pp), 256>>>(x, fs, ss);

    k_gemm<false><<<dim3(4, 6), 256, SMEM_TOT>>>(b2, v2);

    k_out2<<<Bb * Ss, 256>>>(out);
}

// round 7
// speedup vs baseline: 8.7481x; 1.4840x over previous
#include <cuda_runtime.h>
#include <cuda_fp16.h>
#include <cstdint>
#include <math.h>

#define Bb   4
#define Ss   8
#define Ll   350
#define Dd   768
#define Pp   224
#define PP2  448
#define RMAX (Pp * 300)        // second_sep < 300 strictly

// ---------------------------------------------------------------------------
// Scratch (static device globals; no allocation allowed)
// ---------------------------------------------------------------------------
__device__ float g_scores[Pp * Ll];
__device__ float g_emb[PP2 * Dd];
__device__ float g_sc[PP2];
__device__ int   g_poff[Pp + 1];
__device__ int   g_rowmap[RMAX];
// fp16 operands (hi only; 1-term split, measured error budget 15x margin)
__device__ __half g_Ah[RMAX * Dd];
__device__ __half g_Eh[PP2 * Dd];
__device__ __half g_W1h[Dd * Dd];
__device__ __half g_W2h[Dd * Dd];

__device__ __forceinline__ uint32_t smem_u32(const void* p) {
    uint32_t a;
    asm("{ .reg .u64 t; cvta.to.shared.u64 t, %1; cvt.u32.u64 %0, t; }"
        : "=r"(a) : "l"(p));
    return a;
}

__device__ __forceinline__ uint32_t pack2h(__half a, __half b) {
    return (uint32_t)__half_as_ushort(a) | ((uint32_t)__half_as_ushort(b) << 16);
}

__device__ __forceinline__ float tanh_f(float x) {
    x = fminf(15.f, fmaxf(-15.f, x));
    float e = __expf(2.f * x);
    return (e - 1.f) / (e + 1.f);
}

__device__ __forceinline__ void mma_fp16(float* c, const uint32_t* a,
                                         uint32_t b0, uint32_t b1) {
    asm volatile(
        "mma.sync.aligned.m16n8k16.row.col.f32.f16.f16.f32 "
        "{%0,%1,%2,%3}, {%4,%5,%6,%7}, {%8,%9}, {%0,%1,%2,%3};"
        : "+f"(c[0]), "+f"(c[1]), "+f"(c[2]), "+f"(c[3])
        : "r"(a[0]), "r"(a[1]), "r"(a[2]), "r"(a[3]), "r"(b0), "r"(b1));
}

#define LDSM4(r, a) \
    asm volatile("ldmatrix.sync.aligned.m8n8.x4.shared.b16 {%0,%1,%2,%3}, [%4];" \
        : "=r"((r)[0]), "=r"((r)[1]), "=r"((r)[2]), "=r"((r)[3]) : "r"(a))

#define CP16(dst, src) \
    asm volatile("cp.async.cg.shared.global [%0], [%1], 16;" \
                 :: "r"(dst), "l"(src) : "memory")
#define CP_COMMIT() asm volatile("cp.async.commit_group;" ::: "memory")
#define CP_WAIT2()  asm volatile("cp.async.wait_group 2;"  ::: "memory")

// ---------------------------------------------------------------------------
// Kernel 0: pair_embeddings = all_output[:, 0, :]
// ---------------------------------------------------------------------------
__global__ void k_copy(const float* __restrict__ x, float* __restrict__ out) {
    int i = blockIdx.x * 256 + threadIdx.x;
    if (i < Pp * Dd) {
        int p = i / Dd, d = i - p * Dd;
        out[i] = x[(size_t)p * Ll * Dd + d];
    }
}

// ---------------------------------------------------------------------------
// Zero accumulation targets + (block 0) prefix offsets of second_sep
// ---------------------------------------------------------------------------
__global__ void k_init(const int* __restrict__ ss) {
    int i = blockIdx.x * 256 + threadIdx.x;
    if (i < Pp * Ll) g_scores[i] = 0.f;
    if (i < PP2)     g_sc[i]     = 0.f;
    if (blockIdx.x == 0) {
        __shared__ int s[Pp];
        int t = threadIdx.x;
        if (t < Pp) s[t] = ss[t];
        __syncthreads();
        if (t == 0) {
            int a = 0;
            for (int p = 0; p < Pp; p++) { int v = s[p]; s[p] = a; a += v; }
            g_poff[Pp] = a;
        }
        __syncthreads();
        if (t < Pp) g_poff[t] = s[t];
    }
}

// ---------------------------------------------------------------------------
// Compact + convert A: rows (p, l<ss[p]) -> g_Ah (fp16), row map
// ---------------------------------------------------------------------------
__global__ __launch_bounds__(192) void k_convA(const float* __restrict__ x,
                                               const int* __restrict__ ss) {
    int l = blockIdx.x, p = blockIdx.y;
    if (l >= ss[p]) return;
    int r = g_poff[p] + l;
    int tid = threadIdx.x;
    if (tid == 0) g_rowmap[r] = p * Ll + l;
    float4 v = *reinterpret_cast<const float4*>(
        x + ((size_t)p * Ll + l) * Dd + tid * 4);
    size_t off = ((size_t)r * Dd + tid * 4) * 2;
    *reinterpret_cast<uint2*>(reinterpret_cast<char*>(g_Ah) + off) =
        make_uint2(pack2h(__float2half(v.x), __float2half(v.y)),
                   pack2h(__float2half(v.z), __float2half(v.w)));
}

// ---------------------------------------------------------------------------
// Weight prep: W[k][n] -> WT[n][k], fp16
// ---------------------------------------------------------------------------
__global__ __launch_bounds__(256) void k_convW(const float* __restrict__ W1,
                                               const float* __restrict__ W2) {
    __shared__ float s[64][65];
    int k0 = blockIdx.x * 64, n0 = blockIdx.y * 64;
    const float* W = blockIdx.z ? W2 : W1;
    __half* OH = blockIdx.z ? g_W2h : g_W1h;
    int tid = threadIdx.x;
    int nl = tid & 63, kl = tid >> 6;
    #pragma unroll
    for (int j = 0; j < 16; j++)
        s[kl + j * 4][nl] = W[(size_t)(k0 + kl + j * 4) * Dd + n0 + nl];
    __syncthreads();
    int q = tid & 31, nr = tid >> 5;
    #pragma unroll
    for (int j = 0; j < 8; j++) {
        int n = nr + j * 8;
        __half h0 = __float2half(s[2 * q][n]);
        __half h1 = __float2half(s[2 * q + 1][n]);
        size_t off = (size_t)(n0 + n) * Dd + k0 + 2 * q;
        *reinterpret_cast<uint32_t*>(reinterpret_cast<char*>(OH) + off * 2) = pack2h(h0, h1);
    }
}

// ---------------------------------------------------------------------------
// Fused HMMA GEMM (pure fp16), cp.async 4-stage, ldmatrix fragments.
// grid = (row tiles, 6 n-chunks). CTA: 128 rows x 128 N, BK=32 stages.
// Per-row tanh(acc+b)*v partials atomicAdd'ed to output.
// ---------------------------------------------------------------------------
#define BK      32
#define STRIDE  80
#define TILEB   10240
#define STAGEB  20480          // Ah | Bh
#define NST     4
#define SMEM_TOT (NST * STAGEB + 1024)

template <bool COMPACT>
__global__ __launch_bounds__(256) void k_gemm(
    const float* __restrict__ bvec, const float* __restrict__ vvec)
{
    extern __shared__ char smem[];
    int tid = threadIdx.x;
    int l0 = blockIdx.x * 128;
    int nc = blockIdx.y;

    int R = COMPACT ? g_poff[Pp] : PP2;
    if (l0 >= R) return;

    const __half* AH = COMPACT ? g_Ah : g_Eh;
    const __half* WH = COMPACT ? g_W1h : g_W2h;
    float* outp = COMPACT ? g_scores : g_sc;

    uint32_t sb = smem_u32(smem);

    // fixed per-thread copy lanes: rows r0,r1; 16B chunk q
    int q = tid & 3, r0 = tid >> 2, r1 = r0 + 64;
    int gr0 = l0 + r0; if (gr0 >= R) gr0 = R - 1;
    int gr1 = l0 + r1; if (gr1 >= R) gr1 = R - 1;
    const char* sA0 = reinterpret_cast<const char*>(AH + (size_t)gr0 * Dd) + q * 16;
    const char* sA1 = reinterpret_cast<const char*>(AH + (size_t)gr1 * Dd) + q * 16;
    const char* sB0 = reinterpret_cast<const char*>(WH + (size_t)(nc * 128 + r0) * Dd) + q * 16;
    const char* sB1 = reinterpret_cast<const char*>(WH + (size_t)(nc * 128 + r1) * Dd) + q * 16;
    uint32_t d0 = sb + r0 * STRIDE + q * 16;
    uint32_t d1 = sb + r1 * STRIDE + q * 16;

    auto FILL = [&](int s, int kc) {
        uint32_t stg = s * STAGEB;
        int ko = kc * 64;                                 // bytes along k
        CP16(d0 + stg,         sA0 + ko);
        CP16(d1 + stg,         sA1 + ko);
        CP16(d0 + stg + TILEB, sB0 + ko);
        CP16(d1 + stg + TILEB, sB1 + ko);
    };

    int warp = tid >> 5, lane = tid & 31;
    int g = lane >> 2, t = lane & 3;
    int m0 = (warp >> 1) * 32;
    int wn = warp & 1;
    int n0w = wn * 64;

    // ldmatrix lane offsets (within a tile, bytes)
    int aoff = ((lane & 7) + ((lane >> 3) & 1) * 8) * STRIDE + (lane >> 4) * 16;
    int boff = ((lane >> 4) * 8 + (lane & 7)) * STRIDE + ((lane >> 3) & 1) * 16;

    float acc[2][8][4];
    #pragma unroll
    for (int sm = 0; sm < 2; sm++)
        #pragma unroll
        for (int ns = 0; ns < 8; ns++)
            #pragma unroll
            for (int j = 0; j < 4; j++) acc[sm][ns][j] = 0.f;

    auto COMPUTE = [&](int st) {
        uint32_t base = sb + st * STAGEB;
        #pragma unroll
        for (int kk = 0; kk < BK; kk += 16) {
            uint32_t ah[2][4];
            #pragma unroll
            for (int sm = 0; sm < 2; sm++)
                LDSM4(ah[sm], base + (m0 + sm * 16) * STRIDE + aoff + kk * 2);
            #pragma unroll
            for (int ns2 = 0; ns2 < 4; ns2++) {
                uint32_t bh[4];
                LDSM4(bh, base + TILEB + (n0w + ns2 * 16) * STRIDE + boff + kk * 2);
                #pragma unroll
                for (int sm = 0; sm < 2; sm++) {
                    mma_fp16(acc[sm][2 * ns2],     ah[sm], bh[0], bh[1]);
                    mma_fp16(acc[sm][2 * ns2 + 1], ah[sm], bh[2], bh[3]);
                }
            }
        }
    };

    FILL(0, 0); CP_COMMIT();
    FILL(1, 1); CP_COMMIT();
    FILL(2, 2); CP_COMMIT();

    for (int kc = 0; kc < 24; kc++) {
        CP_WAIT2();
        __syncthreads();
        COMPUTE(kc & 3);
        if (kc < 21) FILL((kc + 3) & 3, kc + 3);
        CP_COMMIT();
    }

    // fused epilogue: tanh(acc + b) * v -> per-row partials (this n-chunk)
    float partial[4] = {0.f, 0.f, 0.f, 0.f};
    #pragma unroll
    for (int sm = 0; sm < 2; sm++)
        #pragma unroll
        for (int ns = 0; ns < 8; ns++) {
            int col = nc * 128 + n0w + ns * 8 + 2 * t;
            float bb0 = __ldg(&bvec[col]), bb1 = __ldg(&bvec[col + 1]);
            float vv0 = __ldg(&vvec[col]), vv1 = __ldg(&vvec[col + 1]);
            partial[sm * 2 + 0] += tanh_f(acc[sm][ns][0] + bb0) * vv0
                                 + tanh_f(acc[sm][ns][1] + bb1) * vv1;
            partial[sm * 2 + 1] += tanh_f(acc[sm][ns][2] + bb0) * vv0
                                 + tanh_f(acc[sm][ns][3] + bb1) * vv1;
        }

    #pragma unroll
    for (int j = 0; j < 4; j++) {
        partial[j] += __shfl_xor_sync(0xffffffffu, partial[j], 1);
        partial[j] += __shfl_xor_sync(0xffffffffu, partial[j], 2);
    }
    float* red = reinterpret_cast<float*>(smem + NST * STAGEB);
    __syncthreads();
    if (t == 0) {
        red[wn * 128 + m0 + g]      = partial[0];
        red[wn * 128 + m0 + 8 + g]  = partial[1];
        red[wn * 128 + m0 + 16 + g] = partial[2];
        red[wn * 128 + m0 + 24 + g] = partial[3];
    }
    __syncthreads();
    if (tid < 128) {
        int r = l0 + tid;
        if (r < R) {
            float val = red[tid] + red[128 + tid];
            int oi = COMPACT ? g_rowmap[r] : r;
            atomicAdd(&outp[oi], val);
        }
    }
}

// ---------------------------------------------------------------------------
// Masked softmax pooling; emits fp16 emb; x4 unrolled weighted sum
// ---------------------------------------------------------------------------
__global__ __launch_bounds__(256) void k_pool(const float* __restrict__ x,
                                              const int* __restrict__ fs,
                                              const int* __restrict__ ssp)
{
    int p   = blockIdx.y;
    int sgi = blockIdx.x;
    int f = fs[p], s2 = ssp[p];
    int lo = sgi ? f + 1 : 1;
    int hi = sgi ? s2 : f;
    int cnt = hi - lo;

    __shared__ float w[160];
    __shared__ float red[256];
    int tid = threadIdx.x;

    const float* sc = g_scores + p * Ll + lo;

    float lm = -1e30f;
    for (int i = tid; i < cnt; i += 256) lm = fmaxf(lm, sc[i]);
    red[tid] = lm; __syncthreads();
    for (int o = 128; o > 0; o >>= 1) {
        if (tid < o) red[tid] = fmaxf(red[tid], red[tid + o]);
        __syncthreads();
    }
    float smax = red[0];
    __syncthreads();

    float le = 0.f;
    for (int i = tid; i < cnt; i += 256) {
        float e = __expf(sc[i] - smax);
        w[i] = e;
        le += e;
    }
    red[tid] = le; __syncthreads();
    for (int o = 128; o > 0; o >>= 1) {
        if (tid < o) red[tid] += red[tid + o];
        __syncthreads();
    }
    float inv = 1.0f / red[0];
    __syncthreads();
    for (int i = tid; i < cnt; i += 256) w[i] *= inv;
    __syncthreads();

    float e0 = 0.f, e1 = 0.f, e2 = 0.f;
    const float* xr = x + ((size_t)p * Ll + lo) * Dd;
    int i = 0;
    for (; i + 4 <= cnt; i += 4) {
        const float* r0 = xr + (size_t)i * Dd;
        const float* r1 = r0 + Dd;
        const float* r2 = r1 + Dd;
        const float* r3 = r2 + Dd;
        float w0 = w[i], w1 = w[i + 1], w2 = w[i + 2], w3 = w[i + 3];
        e0 += w0 * r0[tid]       + w1 * r1[tid]       + w2 * r2[tid]       + w3 * r3[tid];
        e1 += w0 * r0[tid + 256] + w1 * r1[tid + 256] + w2 * r2[tid + 256] + w3 * r3[tid + 256];
        e2 += w0 * r0[tid + 512] + w1 * r1[tid + 512] + w2 * r2[tid + 512] + w3 * r3[tid + 512];
    }
    for (; i < cnt; i++) {
        float wl = w[i];
        const float* row = xr + (size_t)i * Dd;
        e0 += wl * row[tid];
        e1 += wl * row[tid + 256];
        e2 += wl * row[tid + 512];
    }
    int rowi = 2 * p + sgi;
    float* er = g_emb + (size_t)rowi * Dd;
    er[tid]       = e0;
    er[tid + 256] = e1;
    er[tid + 512] = e2;
    g_Eh[(size_t)rowi * Dd + tid]       = __float2half(e0);
    g_Eh[(size_t)rowi * Dd + tid + 256] = __float2half(e1);
    g_Eh[(size_t)rowi * Dd + tid + 512] = __float2half(e2);
}

// ---------------------------------------------------------------------------
// Segment softmax + weighted sum
// ---------------------------------------------------------------------------
__global__ void k_out2(float* __restrict__ out) {
    int seg = blockIdx.x;
    int tid = threadIdx.x;
    __shared__ int   mem[14];
    __shared__ float wv[14];

    if (tid == 0) {
        int c = 0;
        for (int idx = 0; idx < PP2; idx++) {
            int pp = idx >> 1, cc = idx & 1;
            int z = pp / 56, r = pp % 56, j = r / 7, m = r % 7;
            int k = m + (m >= j ? 1 : 0);
            int sg = z * 8 + (cc == 0 ? j : k);
            if (sg == seg && c < 14) mem[c++] = idx;
        }
        float mx = -1e30f;
        for (int i = 0; i < 14; i++) mx = fmaxf(mx, g_sc[mem[i]]);
        float den = 0.f;
        for (int i = 0; i < 14; i++) {
            float e = __expf(g_sc[mem[i]] - mx);
            wv[i] = e;
            den += e;
        }
        float inv = 1.f / den;
        for (int i = 0; i < 14; i++) wv[i] *= inv;
    }
    __syncthreads();

    for (int d = tid; d < Dd; d += 256) {
        float a = 0.f;
        #pragma unroll
        for (int i = 0; i < 14; i++)
            a += wv[i] * g_emb[(size_t)mem[i] * Dd + d];
        out[Pp * Dd + seg * Dd + d] = a;
    }
}

// ---------------------------------------------------------------------------
// Launch
// ---------------------------------------------------------------------------
extern "C" void kernel_launch(void* const* d_in, const int* in_sizes, int n_in,
                              void* d_out, int out_size) {
    const float* x   = (const float*)d_in[0];
    const int*   fs  = (const int*)  d_in[1];
    const int*   ss  = (const int*)  d_in[2];
    const float* W1  = (const float*)d_in[3];
    const float* b1  = (const float*)d_in[4];
    const float* v1  = (const float*)d_in[5];
    const float* W2  = (const float*)d_in[7];
    const float* b2  = (const float*)d_in[8];
    const float* v2  = (const float*)d_in[9];
    float* out = (float*)d_out;

    static bool attr_done = false;
    if (!attr_done) {
        cudaFuncSetAttribute(k_gemm<true>,
            cudaFuncAttributeMaxDynamicSharedMemorySize, SMEM_TOT);
        cudaFuncSetAttribute(k_gemm<false>,
            cudaFuncAttributeMaxDynamicSharedMemorySize, SMEM_TOT);
        attr_done = true;
    }

    k_copy<<<(Pp * Dd + 255) / 256, 256>>>(x, out);
    k_init<<<(Pp * Ll + 255) / 256, 256>>>(ss);
    k_convW<<<dim3(12, 12, 2), 256>>>(W1, W2);
    k_convA<<<dim3(Ll, Pp), 192>>>(x, ss);

    k_gemm<true><<<dim3((RMAX + 127) / 128, 6), 256, SMEM_TOT>>>(b1, v1);

    k_pool<<<dim3(2, Pp), 256>>>(x, fs, ss);

    k_gemm<false><<<dim3(4, 6), 256, SMEM_TOT>>>(b2, v2);

    k_out2<<<Bb * Ss, 256>>>(out);
}

// round 8
// speedup vs baseline: 11.0974x; 1.2686x over previous
#include <cuda_runtime.h>
#include <cuda_fp16.h>
#include <cstdint>
#include <math.h>

#define Bb   4
#define Ss   8
#define Ll   350
#define Dd   768
#define Pp   224
#define PP2  448
#define RMAX (Pp * 300)        // second_sep < 300 strictly

// ---------------------------------------------------------------------------
// Scratch (static device globals; no allocation allowed)
// ---------------------------------------------------------------------------
__device__ float g_scores[Pp * Ll];
__device__ float g_emb[PP2 * Dd];
__device__ float g_sc[PP2];
__device__ int   g_poff[Pp + 1];
__device__ int   g_rowmap[RMAX];
__device__ __half g_Ah[RMAX * Dd];
__device__ __half g_Eh[PP2 * Dd];
__device__ __half g_W1h[Dd * Dd];
__device__ __half g_W2h[Dd * Dd];

__device__ __forceinline__ uint32_t smem_u32(const void* p) {
    uint32_t a;
    asm("{ .reg .u64 t; cvta.to.shared.u64 t, %1; cvt.u32.u64 %0, t; }"
        : "=r"(a) : "l"(p));
    return a;
}

__device__ __forceinline__ uint32_t pack2h(__half a, __half b) {
    return (uint32_t)__half_as_ushort(a) | ((uint32_t)__half_as_ushort(b) << 16);
}

__device__ __forceinline__ float tanh_f(float x) {
    x = fminf(15.f, fmaxf(-15.f, x));
    float e = __expf(2.f * x);
    return (e - 1.f) / (e + 1.f);
}

__device__ __forceinline__ void mma_fp16(float* c, const uint32_t* a,
                                         uint32_t b0, uint32_t b1) {
    asm volatile(
        "mma.sync.aligned.m16n8k16.row.col.f32.f16.f16.f32 "
        "{%0,%1,%2,%3}, {%4,%5,%6,%7}, {%8,%9}, {%0,%1,%2,%3};"
        : "+f"(c[0]), "+f"(c[1]), "+f"(c[2]), "+f"(c[3])
        : "r"(a[0]), "r"(a[1]), "r"(a[2]), "r"(a[3]), "r"(b0), "r"(b1));
}

#define LDSM4(r, a) \
    asm volatile("ldmatrix.sync.aligned.m8n8.x4.shared.b16 {%0,%1,%2,%3}, [%4];" \
        : "=r"((r)[0]), "=r"((r)[1]), "=r"((r)[2]), "=r"((r)[3]) : "r"(a))

#define CP16(dst, src) \
    asm volatile("cp.async.cg.shared.global [%0], [%1], 16;" \
                 :: "r"(dst), "l"(src) : "memory")
#define CP_COMMIT() asm volatile("cp.async.commit_group;" ::: "memory")
#define CP_WAIT1()  asm volatile("cp.async.wait_group 1;"  ::: "memory")

// ---------------------------------------------------------------------------
// k_init: zero accum targets, pair_embeddings copy, prefix offsets, rowmap
// ---------------------------------------------------------------------------
__global__ void k_init(const float* __restrict__ x, const int* __restrict__ ss,
                       float* __restrict__ out) {
    int i = blockIdx.x * 256 + threadIdx.x;
    if (i < Pp * Ll) g_scores[i] = 0.f;
    if (i < PP2)     g_sc[i]     = 0.f;
    if (i < Pp * Dd) {
        int p = i / Dd, d = i - p * Dd;
        out[i] = x[(size_t)p * Ll * Dd + d];
    }
    if (blockIdx.x == 0) {
        __shared__ int s[Pp];
        int t = threadIdx.x;
        if (t < Pp) s[t] = ss[t];
        __syncthreads();
        if (t == 0) {
            int a = 0;
            for (int p = 0; p < Pp; p++) { int v = s[p]; s[p] = a; a += v; }
            g_poff[Pp] = a;
        }
        __syncthreads();
        if (t < Pp) {
            int base = s[t];
            g_poff[t] = base;
            int cnt = ss[t];
            int src = t * Ll;
            for (int l = 0; l < cnt; l++) g_rowmap[base + l] = src + l;
        }
    }
}

// ---------------------------------------------------------------------------
// convA: grid-stride conversion of compacted rows to fp16 via rowmap
// ---------------------------------------------------------------------------
__global__ __launch_bounds__(256) void k_convA(const float* __restrict__ x) {
    int R = g_poff[Pp];
    int total = R * 192;                     // 192 float4 units per row
    int stride = gridDim.x * 256;
    for (int i = blockIdx.x * 256 + threadIdx.x; i < total; i += stride) {
        int r = i / 192, c = i - r * 192;
        const float4 v = *reinterpret_cast<const float4*>(
            x + (size_t)g_rowmap[r] * Dd + c * 4);
        *reinterpret_cast<uint2*>(
            reinterpret_cast<char*>(g_Ah) + ((size_t)r * Dd + c * 4) * 2) =
            make_uint2(pack2h(__float2half(v.x), __float2half(v.y)),
                       pack2h(__float2half(v.z), __float2half(v.w)));
    }
}

// ---------------------------------------------------------------------------
// Weight prep: W[k][n] -> WT[n][k], fp16
// ---------------------------------------------------------------------------
__global__ __launch_bounds__(256) void k_convW(const float* __restrict__ W1,
                                               const float* __restrict__ W2) {
    __shared__ float s[64][65];
    int k0 = blockIdx.x * 64, n0 = blockIdx.y * 64;
    const float* W = blockIdx.z ? W2 : W1;
    __half* OH = blockIdx.z ? g_W2h : g_W1h;
    int tid = threadIdx.x;
    int nl = tid & 63, kl = tid >> 6;
    #pragma unroll
    for (int j = 0; j < 16; j++)
        s[kl + j * 4][nl] = W[(size_t)(k0 + kl + j * 4) * Dd + n0 + nl];
    __syncthreads();
    int q = tid & 31, nr = tid >> 5;
    #pragma unroll
    for (int j = 0; j < 8; j++) {
        int n = nr + j * 8;
        __half h0 = __float2half(s[2 * q][n]);
        __half h1 = __float2half(s[2 * q + 1][n]);
        size_t off = (size_t)(n0 + n) * Dd + k0 + 2 * q;
        *reinterpret_cast<uint32_t*>(reinterpret_cast<char*>(OH) + off * 2) = pack2h(h0, h1);
    }
}

// ---------------------------------------------------------------------------
// Fused HMMA GEMM (pure fp16), BK=64, 3-stage cp.async, ldmatrix.
// grid = (row tiles, 6 n-chunks). CTA: 128 rows x 128 N, 12 K-stages.
// Per-row tanh(acc+b)*v partials atomicAdd'ed to output.
// ---------------------------------------------------------------------------
#define BKB     128            // bytes along k per stage (64 halves)
#define STRIDE  144            // padded row stride: 36 banks -> 4r mod 32 pattern
#define TILEB   18432          // 128 * 144
#define STAGEB  36864          // A | B
#define NST     3
#define SMEM_TOT (NST * STAGEB + 1024)

template <bool COMPACT>
__global__ __launch_bounds__(256) void k_gemm(
    const float* __restrict__ bvec, const float* __restrict__ vvec)
{
    extern __shared__ char smem[];
    int tid = threadIdx.x;
    int l0 = blockIdx.x * 128;
    int nc = blockIdx.y;

    int R = COMPACT ? g_poff[Pp] : PP2;
    if (l0 >= R) return;

    const __half* AH = COMPACT ? g_Ah : g_Eh;
    const __half* WH = COMPACT ? g_W1h : g_W2h;
    float* outp = COMPACT ? g_scores : g_sc;

    uint32_t sb = smem_u32(smem);

    // copy lanes: chunk q (16B of the 128B k-row), rows rb, rb+32, rb+64, rb+96
    int q = tid & 7, rb = tid >> 3;
    const char *pa[4], *pb[4];
    uint32_t pd[4];
    #pragma unroll
    for (int j = 0; j < 4; j++) {
        int row = rb + j * 32;
        int gr = l0 + row; if (gr >= R) gr = R - 1;
        pa[j] = reinterpret_cast<const char*>(AH + (size_t)gr * Dd) + q * 16;
        pb[j] = reinterpret_cast<const char*>(WH + (size_t)(nc * 128 + row) * Dd) + q * 16;
        pd[j] = sb + row * STRIDE + q * 16;
    }

    auto FILL = [&](int s, int kc) {
        uint32_t stg = s * STAGEB;
        int ko = kc * BKB;
        #pragma unroll
        for (int j = 0; j < 4; j++) {
            CP16(pd[j] + stg,         pa[j] + ko);
            CP16(pd[j] + stg + TILEB, pb[j] + ko);
        }
    };

    int warp = tid >> 5, lane = tid & 31;
    int g = lane >> 2, t = lane & 3;
    int m0 = (warp >> 1) * 32;
    int wn = warp & 1;
    int n0w = wn * 64;

    int aoff = ((lane & 7) + ((lane >> 3) & 1) * 8) * STRIDE + (lane >> 4) * 16;
    int boff = ((lane >> 4) * 8 + (lane & 7)) * STRIDE + ((lane >> 3) & 1) * 16;

    float acc[2][8][4];
    #pragma unroll
    for (int sm = 0; sm < 2; sm++)
        #pragma unroll
        for (int ns = 0; ns < 8; ns++)
            #pragma unroll
            for (int j = 0; j < 4; j++) acc[sm][ns][j] = 0.f;

    auto COMPUTE = [&](int st) {
        uint32_t base = sb + st * STAGEB;
        #pragma unroll
        for (int kk = 0; kk < 64; kk += 16) {
            uint32_t ah[2][4];
            #pragma unroll
            for (int sm = 0; sm < 2; sm++)
                LDSM4(ah[sm], base + (m0 + sm * 16) * STRIDE + aoff + kk * 2);
            #pragma unroll
            for (int ns2 = 0; ns2 < 4; ns2++) {
                uint32_t bh[4];
                LDSM4(bh, base + TILEB + (n0w + ns2 * 16) * STRIDE + boff + kk * 2);
                #pragma unroll
                for (int sm = 0; sm < 2; sm++) {
                    mma_fp16(acc[sm][2 * ns2],     ah[sm], bh[0], bh[1]);
                    mma_fp16(acc[sm][2 * ns2 + 1], ah[sm], bh[2], bh[3]);
                }
            }
        }
    };

    FILL(0, 0); CP_COMMIT();
    FILL(1, 1); CP_COMMIT();

    for (int kc = 0; kc < 12; kc++) {
        CP_WAIT1();
        __syncthreads();
        COMPUTE(kc % 3);
        if (kc < 10) FILL((kc + 2) % 3, kc + 2);
        CP_COMMIT();
    }

    // fused epilogue: tanh(acc + b) * v -> per-row partials (this n-chunk)
    float partial[4] = {0.f, 0.f, 0.f, 0.f};
    #pragma unroll
    for (int sm = 0; sm < 2; sm++)
        #pragma unroll
        for (int ns = 0; ns < 8; ns++) {
            int col = nc * 128 + n0w + ns * 8 + 2 * t;
            float bb0 = __ldg(&bvec[col]), bb1 = __ldg(&bvec[col + 1]);
            float vv0 = __ldg(&vvec[col]), vv1 = __ldg(&vvec[col + 1]);
            partial[sm * 2 + 0] += tanh_f(acc[sm][ns][0] + bb0) * vv0
                                 + tanh_f(acc[sm][ns][1] + bb1) * vv1;
            partial[sm * 2 + 1] += tanh_f(acc[sm][ns][2] + bb0) * vv0
                                 + tanh_f(acc[sm][ns][3] + bb1) * vv1;
        }

    #pragma unroll
    for (int j = 0; j < 4; j++) {
        partial[j] += __shfl_xor_sync(0xffffffffu, partial[j], 1);
        partial[j] += __shfl_xor_sync(0xffffffffu, partial[j], 2);
    }
    float* red = reinterpret_cast<float*>(smem + NST * STAGEB);
    __syncthreads();
    if (t == 0) {
        red[wn * 128 + m0 + g]      = partial[0];
        red[wn * 128 + m0 + 8 + g]  = partial[1];
        red[wn * 128 + m0 + 16 + g] = partial[2];
        red[wn * 128 + m0 + 24 + g] = partial[3];
    }
    __syncthreads();
    if (tid < 128) {
        int r = l0 + tid;
        if (r < R) {
            float val = red[tid] + red[128 + tid];
            int oi = COMPACT ? g_rowmap[r] : r;
            atomicAdd(&outp[oi], val);
        }
    }
}

// ---------------------------------------------------------------------------
// Masked softmax pooling reading fp16 g_Ah (compact rows). 192 threads:
// thread t owns d = 4t..4t+3 (uint2 loads). Emits fp32 emb + fp16 emb.
// ---------------------------------------------------------------------------
__global__ __launch_bounds__(192) void k_pool(const int* __restrict__ fs,
                                              const int* __restrict__ ssp)
{
    int p   = blockIdx.y;
    int sgi = blockIdx.x;
    int f = fs[p], s2 = ssp[p];
    int lo = sgi ? f + 1 : 1;
    int hi = sgi ? s2 : f;
    int cnt = hi - lo;                      // 4..148

    __shared__ float w[152];
    __shared__ float wred[8];
    __shared__ float bc;
    int tid = threadIdx.x;
    int lane = tid & 31, wid = tid >> 5;

    const float* sc = g_scores + p * Ll + lo;

    // max (cnt <= 148 < 192: single pass)
    float lm = (tid < cnt) ? sc[tid] : -1e30f;
    #pragma unroll
    for (int o = 16; o > 0; o >>= 1) lm = fmaxf(lm, __shfl_xor_sync(~0u, lm, o));
    if (lane == 0) wred[wid] = lm;
    __syncthreads();
    if (tid == 0) {
        float m = wred[0];
        #pragma unroll
        for (int j = 1; j < 6; j++) m = fmaxf(m, wred[j]);
        bc = m;
    }
    __syncthreads();
    float smax = bc;

    float le = 0.f;
    if (tid < cnt) { float e = __expf(sc[tid] - smax); w[tid] = e; le = e; }
    #pragma unroll
    for (int o = 16; o > 0; o >>= 1) le += __shfl_xor_sync(~0u, le, o);
    if (lane == 0) wred[wid] = le;
    __syncthreads();
    if (tid == 0) {
        float s = 0.f;
        #pragma unroll
        for (int j = 1; j < 6; j++) s += wred[j];
        bc = 1.0f / (s + wred[0]);
    }
    __syncthreads();
    float inv = bc;
    if (tid < cnt) w[tid] *= inv;
    __syncthreads();

    // weighted sum over fp16 rows of g_Ah (compact, contiguous in l)
    int r0 = g_poff[p] + lo;
    const char* xr = reinterpret_cast<const char*>(g_Ah) + ((size_t)r0 * Dd) * 2 + tid * 8;
    float e0 = 0.f, e1 = 0.f, e2 = 0.f, e3 = 0.f;
    int i = 0;
    for (; i + 2 <= cnt; i += 2) {
        uint2 u0 = *reinterpret_cast<const uint2*>(xr + (size_t)i * Dd * 2);
        uint2 u1 = *reinterpret_cast<const uint2*>(xr + (size_t)(i + 1) * Dd * 2);
        float w0 = w[i], w1 = w[i + 1];
        float2 a0 = __half22float2(*reinterpret_cast<__half2*>(&u0.x));
        float2 a1 = __half22float2(*reinterpret_cast<__half2*>(&u0.y));
        float2 b0 = __half22float2(*reinterpret_cast<__half2*>(&u1.x));
        float2 b1 = __half22float2(*reinterpret_cast<__half2*>(&u1.y));
        e0 += w0 * a0.x + w1 * b0.x;
        e1 += w0 * a0.y + w1 * b0.y;
        e2 += w0 * a1.x + w1 * b1.x;
        e3 += w0 * a1.y + w1 * b1.y;
    }
    for (; i < cnt; i++) {
        uint2 u0 = *reinterpret_cast<const uint2*>(xr + (size_t)i * Dd * 2);
        float w0 = w[i];
        float2 a0 = __half22float2(*reinterpret_cast<__half2*>(&u0.x));
        float2 a1 = __half22float2(*reinterpret_cast<__half2*>(&u0.y));
        e0 += w0 * a0.x; e1 += w0 * a0.y; e2 += w0 * a1.x; e3 += w0 * a1.y;
    }

    int rowi = 2 * p + sgi;
    float4* er = reinterpret_cast<float4*>(g_emb + (size_t)rowi * Dd);
    er[tid] = make_float4(e0, e1, e2, e3);
    *reinterpret_cast<uint2*>(
        reinterpret_cast<char*>(g_Eh) + ((size_t)rowi * Dd) * 2 + tid * 8) =
        make_uint2(pack2h(__float2half(e0), __float2half(e1)),
                   pack2h(__float2half(e2), __float2half(e3)));
}

// ---------------------------------------------------------------------------
// Segment softmax + weighted sum
// ---------------------------------------------------------------------------
__global__ void k_out2(float* __restrict__ out) {
    int seg = blockIdx.x;
    int tid = threadIdx.x;
    __shared__ int   mem[14];
    __shared__ float wv[14];

    if (tid == 0) {
        int c = 0;
        for (int idx = 0; idx < PP2; idx++) {
            int pp = idx >> 1, cc = idx & 1;
            int z = pp / 56, r = pp % 56, j = r / 7, m = r % 7;
            int k = m + (m >= j ? 1 : 0);
            int sg = z * 8 + (cc == 0 ? j : k);
            if (sg == seg && c < 14) mem[c++] = idx;
        }
        float mx = -1e30f;
        for (int i = 0; i < 14; i++) mx = fmaxf(mx, g_sc[mem[i]]);
        float den = 0.f;
        for (int i = 0; i < 14; i++) {
            float e = __expf(g_sc[mem[i]] - mx);
            wv[i] = e;
            den += e;
        }
        float inv = 1.f / den;
        for (int i = 0; i < 14; i++) wv[i] *= inv;
    }
    __syncthreads();

    for (int d = tid; d < Dd; d += 256) {
        float a = 0.f;
        #pragma unroll
        for (int i = 0; i < 14; i++)
            a += wv[i] * g_emb[(size_t)mem[i] * Dd + d];
        out[Pp * Dd + seg * Dd + d] = a;
    }
}

// ---------------------------------------------------------------------------
// Launch
// ---------------------------------------------------------------------------
extern "C" void kernel_launch(void* const* d_in, const int* in_sizes, int n_in,
                              void* d_out, int out_size) {
    const float* x   = (const float*)d_in[0];
    const int*   fs  = (const int*)  d_in[1];
    const int*   ss  = (const int*)  d_in[2];
    const float* W1  = (const float*)d_in[3];
    const float* b1  = (const float*)d_in[4];
    const float* v1  = (const float*)d_in[5];
    const float* W2  = (const float*)d_in[7];
    const float* b2  = (const float*)d_in[8];
    const float* v2  = (const float*)d_in[9];
    float* out = (float*)d_out;

    static bool attr_done = false;
    if (!attr_done) {
        cudaFuncSetAttribute(k_gemm<true>,
            cudaFuncAttributeMaxDynamicSharedMemorySize, SMEM_TOT);
        cudaFuncSetAttribute(k_gemm<false>,
            cudaFuncAttributeMaxDynamicSharedMemorySize, SMEM_TOT);
        attr_done = true;
    }

    k_init<<<(Pp * Dd + 255) / 256, 256>>>(x, ss, out);
    k_convW<<<dim3(12, 12, 2), 256>>>(W1, W2);
    k_convA<<<2048, 256>>>(x);

    k_gemm<true><<<dim3((RMAX + 127) / 128, 6), 256, SMEM_TOT>>>(b1, v1);

    k_pool<<<dim3(2, Pp), 192>>>(fs, ss);

    k_gemm<false><<<dim3(4, 6), 256, SMEM_TOT>>>(b2, v2);

    k_out2<<<Bb * Ss, 256>>>(out);
}

// round 9
// speedup vs baseline: 12.6455x; 1.1395x over previous
#include <cuda_runtime.h>
#include <cuda_fp16.h>
#include <cstdint>
#include <math.h>

#define Bb   4
#define Ss   8
#define Ll   350
#define Dd   768
#define Pp   224
#define PP2  448
#define RMAX (Pp * 300)        // second_sep < 300 strictly

// ---------------------------------------------------------------------------
// Scratch (static device globals; no allocation allowed)
// ---------------------------------------------------------------------------
__device__ float g_scores[Pp * Ll];
__device__ float g_emb[PP2 * Dd];
__device__ float g_sc[PP2];
__device__ int   g_poff[Pp + 1];
__device__ int   g_rowmap[RMAX];
__device__ __half g_Ah[RMAX * Dd];
__device__ __half g_Eh[PP2 * Dd];
__device__ __half g_W1h[Dd * Dd];
__device__ __half g_W2h[Dd * Dd];

__device__ __forceinline__ uint32_t smem_u32(const void* p) {
    uint32_t a;
    asm("{ .reg .u64 t; cvta.to.shared.u64 t, %1; cvt.u32.u64 %0, t; }"
        : "=r"(a) : "l"(p));
    return a;
}

__device__ __forceinline__ uint32_t pack2h(__half a, __half b) {
    return (uint32_t)__half_as_ushort(a) | ((uint32_t)__half_as_ushort(b) << 16);
}

// single-MUFU tanh (rel err ~2^-11; calibrated error budget has 3x margin)
__device__ __forceinline__ float tanh_f(float x) {
    float y;
    asm("tanh.approx.f32 %0, %1;" : "=f"(y) : "f"(x));
    return y;
}

__device__ __forceinline__ void mma_fp16(float* c, const uint32_t* a,
                                         uint32_t b0, uint32_t b1) {
    asm volatile(
        "mma.sync.aligned.m16n8k16.row.col.f32.f16.f16.f32 "
        "{%0,%1,%2,%3}, {%4,%5,%6,%7}, {%8,%9}, {%0,%1,%2,%3};"
        : "+f"(c[0]), "+f"(c[1]), "+f"(c[2]), "+f"(c[3])
        : "r"(a[0]), "r"(a[1]), "r"(a[2]), "r"(a[3]), "r"(b0), "r"(b1));
}

#define LDSM4(r, a) \
    asm volatile("ldmatrix.sync.aligned.m8n8.x4.shared.b16 {%0,%1,%2,%3}, [%4];" \
        : "=r"((r)[0]), "=r"((r)[1]), "=r"((r)[2]), "=r"((r)[3]) : "r"(a))

#define CP16(dst, src) \
    asm volatile("cp.async.cg.shared.global [%0], [%1], 16;" \
                 :: "r"(dst), "l"(src) : "memory")
#define CP_COMMIT() asm volatile("cp.async.commit_group;" ::: "memory")
#define CP_WAIT1()  asm volatile("cp.async.wait_group 1;"  ::: "memory")

// ---------------------------------------------------------------------------
// k_init: (blocks 0..671) zero accum targets, pair_embeddings copy, prefix
// offsets + rowmap; (blocks 672..959) W transpose+fp16 convert.
// ---------------------------------------------------------------------------
__global__ void k_init(const float* __restrict__ x, const int* __restrict__ ss,
                       const float* __restrict__ W1, const float* __restrict__ W2,
                       float* __restrict__ out) {
    __shared__ float s[64][65];
    int bid = blockIdx.x;
    int tid = threadIdx.x;

    if (bid < 672) {
        int i = bid * 256 + tid;
        if (i < Pp * Ll) g_scores[i] = 0.f;
        if (i < PP2)     g_sc[i]     = 0.f;
        if (i < Pp * Dd) {
            int p = i / Dd, d = i - p * Dd;
            out[i] = x[(size_t)p * Ll * Dd + d];
        }
        if (bid == 0) {
            __shared__ int sp[Pp];
            if (tid < Pp) sp[tid] = ss[tid];
            __syncthreads();
            if (tid == 0) {
                int a = 0;
                for (int p = 0; p < Pp; p++) { int v = sp[p]; sp[p] = a; a += v; }
                g_poff[Pp] = a;
            }
            __syncthreads();
            if (tid < Pp) {
                int base = sp[tid];
                g_poff[tid] = base;
                int cnt = ss[tid];
                int src = tid * Ll;
                for (int l = 0; l < cnt; l++) g_rowmap[base + l] = src + l;
            }
        }
    } else {
        int b = bid - 672;              // 288 = 12 x 12 x 2
        int kb = b % 12, nb = (b / 12) % 12, z = b / 144;
        int k0 = kb * 64, n0 = nb * 64;
        const float* W = z ? W2 : W1;
        __half* OH = z ? g_W2h : g_W1h;
        int nl = tid & 63, kl = tid >> 6;
        #pragma unroll
        for (int j = 0; j < 16; j++)
            s[kl + j * 4][nl] = W[(size_t)(k0 + kl + j * 4) * Dd + n0 + nl];
        __syncthreads();
        int q = tid & 31, nr = tid >> 5;
        #pragma unroll
        for (int j = 0; j < 8; j++) {
            int n = nr + j * 8;
            __half h0 = __float2half(s[2 * q][n]);
            __half h1 = __float2half(s[2 * q + 1][n]);
            size_t off = (size_t)(n0 + n) * Dd + k0 + 2 * q;
            *reinterpret_cast<uint32_t*>(reinterpret_cast<char*>(OH) + off * 2) =
                pack2h(h0, h1);
        }
    }
}

// ---------------------------------------------------------------------------
// convA: grid-stride conversion of compacted rows to fp16 via rowmap
// ---------------------------------------------------------------------------
__global__ __launch_bounds__(256) void k_convA(const float* __restrict__ x) {
    int R = g_poff[Pp];
    int total = R * 192;                     // 192 float4 units per row
    int stride = gridDim.x * 256;
    for (int i = blockIdx.x * 256 + threadIdx.x; i < total; i += stride) {
        int r = i / 192, c = i - r * 192;
        const float4 v = *reinterpret_cast<const float4*>(
            x + (size_t)g_rowmap[r] * Dd + c * 4);
        *reinterpret_cast<uint2*>(
            reinterpret_cast<char*>(g_Ah) + ((size_t)r * Dd + c * 4) * 2) =
            make_uint2(pack2h(__float2half(v.x), __float2half(v.y)),
                       pack2h(__float2half(v.z), __float2half(v.w)));
    }
}

// ---------------------------------------------------------------------------
// Fused HMMA GEMM (pure fp16), BK=64, 3-stage cp.async, ldmatrix.
// grid = (row tiles, 6 n-chunks). CTA: 128 rows x 128 N, 12 K-stages.
// Per-row tanh(acc+b)*v partials atomicAdd'ed to output.
// ---------------------------------------------------------------------------
#define BKB     128            // bytes along k per stage (64 halves)
#define STRIDE  144
#define TILEB   18432          // 128 * 144
#define STAGEB  36864          // A | B
#define NST     3
#define SMEM_TOT (NST * STAGEB + 1024)

template <bool COMPACT>
__global__ __launch_bounds__(256) void k_gemm(
    const float* __restrict__ bvec, const float* __restrict__ vvec)
{
    extern __shared__ char smem[];
    int tid = threadIdx.x;
    int l0 = blockIdx.x * 128;
    int nc = blockIdx.y;

    int R = COMPACT ? g_poff[Pp] : PP2;
    if (l0 >= R) return;

    const __half* AH = COMPACT ? g_Ah : g_Eh;
    const __half* WH = COMPACT ? g_W1h : g_W2h;
    float* outp = COMPACT ? g_scores : g_sc;

    uint32_t sb = smem_u32(smem);

    // copy lanes: chunk q (16B of the 128B k-row), rows rb, rb+32, rb+64, rb+96
    int q = tid & 7, rb = tid >> 3;
    const char *pa[4], *pb[4];
    uint32_t pd[4];
    #pragma unroll
    for (int j = 0; j < 4; j++) {
        int row = rb + j * 32;
        int gr = l0 + row; if (gr >= R) gr = R - 1;
        pa[j] = reinterpret_cast<const char*>(AH + (size_t)gr * Dd) + q * 16;
        pb[j] = reinterpret_cast<const char*>(WH + (size_t)(nc * 128 + row) * Dd) + q * 16;
        pd[j] = sb + row * STRIDE + q * 16;
    }

    auto FILL = [&](int s, int kc) {
        uint32_t stg = s * STAGEB;
        int ko = kc * BKB;
        #pragma unroll
        for (int j = 0; j < 4; j++) {
            CP16(pd[j] + stg,         pa[j] + ko);
            CP16(pd[j] + stg + TILEB, pb[j] + ko);
        }
    };

    int warp = tid >> 5, lane = tid & 31;
    int g = lane >> 2, t = lane & 3;
    int m0 = (warp >> 1) * 32;
    int wn = warp & 1;
    int n0w = wn * 64;

    int aoff = ((lane & 7) + ((lane >> 3) & 1) * 8) * STRIDE + (lane >> 4) * 16;
    int boff = ((lane >> 4) * 8 + (lane & 7)) * STRIDE + ((lane >> 3) & 1) * 16;

    float acc[2][8][4];
    #pragma unroll
    for (int sm = 0; sm < 2; sm++)
        #pragma unroll
        for (int ns = 0; ns < 8; ns++)
            #pragma unroll
            for (int j = 0; j < 4; j++) acc[sm][ns][j] = 0.f;

    auto COMPUTE = [&](int st) {
        uint32_t base = sb + st * STAGEB;
        #pragma unroll
        for (int kk = 0; kk < 64; kk += 16) {
            uint32_t ah[2][4];
            #pragma unroll
            for (int sm = 0; sm < 2; sm++)
                LDSM4(ah[sm], base + (m0 + sm * 16) * STRIDE + aoff + kk * 2);
            #pragma unroll
            for (int ns2 = 0; ns2 < 4; ns2++) {
                uint32_t bh[4];
                LDSM4(bh, base + TILEB + (n0w + ns2 * 16) * STRIDE + boff + kk * 2);
                #pragma unroll
                for (int sm = 0; sm < 2; sm++) {
                    mma_fp16(acc[sm][2 * ns2],     ah[sm], bh[0], bh[1]);
                    mma_fp16(acc[sm][2 * ns2 + 1], ah[sm], bh[2], bh[3]);
                }
            }
        }
    };

    FILL(0, 0); CP_COMMIT();
    FILL(1, 1); CP_COMMIT();

    for (int kc = 0; kc < 12; kc++) {
        CP_WAIT1();
        __syncthreads();
        COMPUTE(kc % 3);
        if (kc < 10) FILL((kc + 2) % 3, kc + 2);
        CP_COMMIT();
    }

    // fused epilogue: tanh(acc + b) * v -> per-row partials (this n-chunk)
    float partial[4] = {0.f, 0.f, 0.f, 0.f};
    #pragma unroll
    for (int sm = 0; sm < 2; sm++)
        #pragma unroll
        for (int ns = 0; ns < 8; ns++) {
            int col = nc * 128 + n0w + ns * 8 + 2 * t;
            float bb0 = __ldg(&bvec[col]), bb1 = __ldg(&bvec[col + 1]);
            float vv0 = __ldg(&vvec[col]), vv1 = __ldg(&vvec[col + 1]);
            partial[sm * 2 + 0] += tanh_f(acc[sm][ns][0] + bb0) * vv0
                                 + tanh_f(acc[sm][ns][1] + bb1) * vv1;
            partial[sm * 2 + 1] += tanh_f(acc[sm][ns][2] + bb0) * vv0
                                 + tanh_f(acc[sm][ns][3] + bb1) * vv1;
        }

    #pragma unroll
    for (int j = 0; j < 4; j++) {
        partial[j] += __shfl_xor_sync(0xffffffffu, partial[j], 1);
        partial[j] += __shfl_xor_sync(0xffffffffu, partial[j], 2);
    }
    float* red = reinterpret_cast<float*>(smem + NST * STAGEB);
    __syncthreads();
    if (t == 0) {
        red[wn * 128 + m0 + g]      = partial[0];
        red[wn * 128 + m0 + 8 + g]  = partial[1];
        red[wn * 128 + m0 + 16 + g] = partial[2];
        red[wn * 128 + m0 + 24 + g] = partial[3];
    }
    __syncthreads();
    if (tid < 128) {
        int r = l0 + tid;
        if (r < R) {
            float val = red[tid] + red[128 + tid];
            int oi = COMPACT ? g_rowmap[r] : r;
            atomicAdd(&outp[oi], val);
        }
    }
}

// ---------------------------------------------------------------------------
// Masked softmax pooling reading fp16 g_Ah (compact rows). 192 threads:
// thread t owns d = 4t..4t+3 (uint2 loads). Emits fp32 emb + fp16 emb.
// ---------------------------------------------------------------------------
__global__ __launch_bounds__(192) void k_pool(const int* __restrict__ fs,
                                              const int* __restrict__ ssp)
{
    int p   = blockIdx.y;
    int sgi = blockIdx.x;
    int f = fs[p], s2 = ssp[p];
    int lo = sgi ? f + 1 : 1;
    int hi = sgi ? s2 : f;
    int cnt = hi - lo;                      // 4..148

    __shared__ float w[152];
    __shared__ float wred[8];
    __shared__ float bc;
    int tid = threadIdx.x;
    int lane = tid & 31, wid = tid >> 5;

    const float* sc = g_scores + p * Ll + lo;

    float lm = (tid < cnt) ? sc[tid] : -1e30f;
    #pragma unroll
    for (int o = 16; o > 0; o >>= 1) lm = fmaxf(lm, __shfl_xor_sync(~0u, lm, o));
    if (lane == 0) wred[wid] = lm;
    __syncthreads();
    if (tid == 0) {
        float m = wred[0];
        #pragma unroll
        for (int j = 1; j < 6; j++) m = fmaxf(m, wred[j]);
        bc = m;
    }
    __syncthreads();
    float smax = bc;

    float le = 0.f;
    if (tid < cnt) { float e = __expf(sc[tid] - smax); w[tid] = e; le = e; }
    #pragma unroll
    for (int o = 16; o > 0; o >>= 1) le += __shfl_xor_sync(~0u, le, o);
    if (lane == 0) wred[wid] = le;
    __syncthreads();
    if (tid == 0) {
        float s = 0.f;
        #pragma unroll
        for (int j = 1; j < 6; j++) s += wred[j];
        bc = 1.0f / (s + wred[0]);
    }
    __syncthreads();
    float inv = bc;
    if (tid < cnt) w[tid] *= inv;
    __syncthreads();

    int r0 = g_poff[p] + lo;
    const char* xr = reinterpret_cast<const char*>(g_Ah) + ((size_t)r0 * Dd) * 2 + tid * 8;
    float e0 = 0.f, e1 = 0.f, e2 = 0.f, e3 = 0.f;
    int i = 0;
    for (; i + 2 <= cnt; i += 2) {
        uint2 u0 = *reinterpret_cast<const uint2*>(xr + (size_t)i * Dd * 2);
        uint2 u1 = *reinterpret_cast<const uint2*>(xr + (size_t)(i + 1) * Dd * 2);
        float w0 = w[i], w1 = w[i + 1];
        float2 a0 = __half22float2(*reinterpret_cast<__half2*>(&u0.x));
        float2 a1 = __half22float2(*reinterpret_cast<__half2*>(&u0.y));
        float2 b0 = __half22float2(*reinterpret_cast<__half2*>(&u1.x));
        float2 b1 = __half22float2(*reinterpret_cast<__half2*>(&u1.y));
        e0 += w0 * a0.x + w1 * b0.x;
        e1 += w0 * a0.y + w1 * b0.y;
        e2 += w0 * a1.x + w1 * b1.x;
        e3 += w0 * a1.y + w1 * b1.y;
    }
    for (; i < cnt; i++) {
        uint2 u0 = *reinterpret_cast<const uint2*>(xr + (size_t)i * Dd * 2);
        float w0 = w[i];
        float2 a0 = __half22float2(*reinterpret_cast<__half2*>(&u0.x));
        float2 a1 = __half22float2(*reinterpret_cast<__half2*>(&u0.y));
        e0 += w0 * a0.x; e1 += w0 * a0.y; e2 += w0 * a1.x; e3 += w0 * a1.y;
    }

    int rowi = 2 * p + sgi;
    float4* er = reinterpret_cast<float4*>(g_emb + (size_t)rowi * Dd);
    er[tid] = make_float4(e0, e1, e2, e3);
    *reinterpret_cast<uint2*>(
        reinterpret_cast<char*>(g_Eh) + ((size_t)rowi * Dd) * 2 + tid * 8) =
        make_uint2(pack2h(__float2half(e0), __float2half(e1)),
                   pack2h(__float2half(e2), __float2half(e3)));
}

// ---------------------------------------------------------------------------
// Segment softmax + weighted sum
// ---------------------------------------------------------------------------
__global__ void k_out2(float* __restrict__ out) {
    int seg = blockIdx.x;
    int tid = threadIdx.x;
    __shared__ int   mem[14];
    __shared__ float wv[14];

    if (tid == 0) {
        int c = 0;
        for (int idx = 0; idx < PP2; idx++) {
            int pp = idx >> 1, cc = idx & 1;
            int z = pp / 56, r = pp % 56, j = r / 7, m = r % 7;
            int k = m + (m >= j ? 1 : 0);
            int sg = z * 8 + (cc == 0 ? j : k);
            if (sg == seg && c < 14) mem[c++] = idx;
        }
        float mx = -1e30f;
        for (int i = 0; i < 14; i++) mx = fmaxf(mx, g_sc[mem[i]]);
        float den = 0.f;
        for (int i = 0; i < 14; i++) {
            float e = __expf(g_sc[mem[i]] - mx);
            wv[i] = e;
            den += e;
        }
        float inv = 1.f / den;
        for (int i = 0; i < 14; i++) wv[i] *= inv;
    }
    __syncthreads();

    for (int d = tid; d < Dd; d += 256) {
        float a = 0.f;
        #pragma unroll
        for (int i = 0; i < 14; i++)
            a += wv[i] * g_emb[(size_t)mem[i] * Dd + d];
        out[Pp * Dd + seg * Dd + d] = a;
    }
}

// ---------------------------------------------------------------------------
// Launch
// ---------------------------------------------------------------------------
extern "C" void kernel_launch(void* const* d_in, const int* in_sizes, int n_in,
                              void* d_out, int out_size) {
    const float* x   = (const float*)d_in[0];
    const int*   fs  = (const int*)  d_in[1];
    const int*   ss  = (const int*)  d_in[2];
    const float* W1  = (const float*)d_in[3];
    const float* b1  = (const float*)d_in[4];
    const float* v1  = (const float*)d_in[5];
    const float* W2  = (const float*)d_in[7];
    const float* b2  = (const float*)d_in[8];
    const float* v2  = (const float*)d_in[9];
    float* out = (float*)d_out;

    static bool attr_done = false;
    if (!attr_done) {
        cudaFuncSetAttribute(k_gemm<true>,
            cudaFuncAttributeMaxDynamicSharedMemorySize, SMEM_TOT);
        cudaFuncSetAttribute(k_gemm<false>,
            cudaFuncAttributeMaxDynamicSharedMemorySize, SMEM_TOT);
        attr_done = true;
    }

    k_init<<<960, 256>>>(x, ss, W1, W2, out);
    k_convA<<<2048, 256>>>(x);

    k_gemm<true><<<dim3((RMAX + 127) / 128, 6), 256, SMEM_TOT>>>(b1, v1);

    k_pool<<<dim3(2, Pp), 192>>>(fs, ss);

    k_gemm<false><<<dim3(4, 6), 256, SMEM_TOT>>>(b2, v2);

    k_out2<<<Bb * Ss, 256>>>(out);
}